// round 12
// baseline (speedup 1.0000x reference)
#include <cuda_runtime.h>
#include <cuda_bf16.h>
#include <cuda_fp16.h>
#include <cstdint>

// ---------------------------------------------------------------------------
// GSPN block. B=4, T=1024, D=768, HW=32, DS=48, CHUNK=8.
// Round 12: HMMA same-accumulator reuse distance 1 -> 4 (pass-split subloops);
// LUD/sig gate GEMMs on TM=64 tiles.
// ---------------------------------------------------------------------------

#define Bsz   4
#define Dch   768
#define Tlen  1024
#define DS    48
#define NPIX  1024
#define NTOT  4096
#define C4    (4*Dch)         // 3072
#define MG    (6*C4)          // 18432
#define BTD   (Bsz*Tlen*Dch)

// ------------------------- static scratch ----------------------------------
__device__ float g_x1 [(size_t)Dch*NTOT];
__device__ float g_x2 [(size_t)Dch*NTOT];
__device__ float g_x2t[(size_t)Dch*NTOT];
__device__ __nv_bfloat16 g_gsig[(size_t)3*C4*NTOT];
__device__ __align__(16) __half g_glud[(size_t)3*C4*NTOT];
__device__ __align__(16) __half g_s4 [(size_t)C4*NTOT];
__device__ float g_oc [(size_t)Dch*NTOT];
__device__ float g_act[(size_t)Dch*NTOT];

__device__ __align__(16) __nv_bfloat16 g_xlnh[(size_t)NTOT*Dch], g_xlnl[(size_t)NTOT*Dch];
__device__ __align__(16) __nv_bfloat16 g_wih [Dch*Dch], g_wil [Dch*Dch];
__device__ __align__(16) __nv_bfloat16 g_woh [Dch*Dch], g_wol [Dch*Dch];
__device__ __align__(16) __nv_bfloat16 g_wph [Dch*Dch], g_wpl [Dch*Dch];
__device__ __align__(16) __nv_bfloat16 g_gwh [(size_t)MG*64], g_gwl [(size_t)MG*64];
__device__ __align__(16) __nv_bfloat16 g_xpnh[(size_t)NTOT*64], g_xpnl[(size_t)NTOT*64];
__device__ __align__(16) __nv_bfloat16 g_mnh [(size_t)NTOT*Dch], g_mnl [(size_t)NTOT*Dch];
__device__ __align__(16) __nv_bfloat16 g_anh [(size_t)NTOT*Dch], g_anl [(size_t)NTOT*Dch];

// ------------------------------ helpers ------------------------------------
__device__ __forceinline__ uint32_t smem_u32(const void* p) {
    uint32_t r;
    asm("{ .reg .u64 t; cvta.to.shared.u64 t, %1; cvt.u32.u64 %0, t; }"
        : "=r"(r) : "l"(p));
    return r;
}
__device__ __forceinline__ void cp16(uint32_t saddr, const void* gptr) {
    asm volatile("cp.async.cg.shared.global [%0], [%1], 16;"
        :: "r"(saddr), "l"(gptr));
}
__device__ __forceinline__ void cp_commit() {
    asm volatile("cp.async.commit_group;" ::: "memory");
}
template<int N>
__device__ __forceinline__ void cp_wait() {
    asm volatile("cp.async.wait_group %0;" :: "n"(N) : "memory");
}
__device__ __forceinline__ void ldm4(uint32_t& r0, uint32_t& r1, uint32_t& r2,
                                     uint32_t& r3, uint32_t addr) {
    asm volatile("ldmatrix.sync.aligned.m8n8.x4.shared.b16 {%0,%1,%2,%3}, [%4];"
        : "=r"(r0), "=r"(r1), "=r"(r2), "=r"(r3) : "r"(addr));
}
__device__ __forceinline__ void mma16816(float* c, const uint32_t* a,
                                         const uint32_t* b) {
    asm volatile("mma.sync.aligned.m16n8k16.row.col.f32.bf16.bf16.f32 "
        "{%0,%1,%2,%3}, {%4,%5,%6,%7}, {%8,%9}, {%0,%1,%2,%3};"
        : "+f"(c[0]), "+f"(c[1]), "+f"(c[2]), "+f"(c[3])
        : "r"(a[0]), "r"(a[1]), "r"(a[2]), "r"(a[3]), "r"(b[0]), "r"(b[1]));
}

__device__ __forceinline__ float fast_exp(float x) {
    x = fminf(fmaxf(x, -20.f), 20.f);
    float t = x * 1.4426950408889634f;
    float r = t + 12582912.f;
    int   i = __float_as_int(r) - 0x4B400000;
    float f = t - (r - 12582912.f);
    const float c1=0.69314718056f, c2=0.2402265069f, c3=0.0555041087f,
                c4=0.00961812911f, c5=0.00133335581f;
    float p = fmaf(c5, f, c4);
    p = fmaf(p, f, c3); p = fmaf(p, f, c2); p = fmaf(p, f, c1); p = fmaf(p, f, 1.f);
    return __int_as_float(__float_as_int(p) + (i << 23));
}
__device__ __forceinline__ float fast_rcp(float x) {
    float y = __int_as_float(0x7EF311C3 - __float_as_int(x));
    y = y * (2.0f - x * y);
    y = y * (2.0f - x * y);
    y = y * (2.0f - x * y);
    return y;
}

// ------------------------------ HMMA GEMM ----------------------------------
// C(MxN) = hi/lo passes of A(MxKp) @ B(NxKp)^T, bf16 K-major.
// OUT: 0=fp32, 1=bf16, 2=fp16 storage. TM x 128 tile, 8 warps, BK=32, 3 stages.
// Pass-split nt-subloops: same-acc HMMA reuse distance 4 (was 1).
template<int PASSES, int OUT, int TM, int MAXCTA>
__global__ __launch_bounds__(256, MAXCTA)
void mma_gemm(const __nv_bfloat16* __restrict__ Ahi, const __nv_bfloat16* __restrict__ Alo,
              const __nv_bfloat16* __restrict__ Bhi, const __nv_bfloat16* __restrict__ Blo,
              float* __restrict__ Cf, __nv_bfloat16* __restrict__ Cb,
              __half* __restrict__ Ch, int Kp, int ldc) {
    extern __shared__ __align__(16) char dsm[];
    const int PA = (PASSES == 3) ? 2 : 1;
    const int SA = TM * 64;
    const int SB = 8192;
    const int SSTAGE = PA * SA + PA * SB;
    const int MT = TM / 32;
    const int tid  = threadIdx.x;
    const int wid  = tid >> 5, lane = tid & 31;
    const int wm   = (wid >> 2) * (TM >> 1);
    const int wn   = (wid & 3)  << 5;
    const int bm   = blockIdx.y * TM, bn = blockIdx.x << 7;
    const uint32_t sbase = smem_u32(dsm);
    const int NKB = Kp >> 5;

    auto load_stage = [&](int buf, int kb) {
        const int k0 = kb << 5;
        uint32_t sb = sbase + buf * SSTAGE;
        #pragma unroll
        for (int pl = 0; pl < PA; pl++) {
            const __nv_bfloat16* src = (pl == 0) ? Ahi : Alo;
            uint32_t pb = sb + pl * SA;
            #pragma unroll
            for (int i = tid; i < TM * 4; i += 256) {
                int r = i >> 2, c = i & 3;
                cp16(pb + (r << 6) + ((uint32_t)(c ^ ((r >> 1) & 3)) << 4),
                     src + (size_t)(bm + r) * Kp + k0 + (c << 3));
            }
        }
        #pragma unroll
        for (int pl = 0; pl < PA; pl++) {
            const __nv_bfloat16* src = (pl == 0) ? Bhi : Blo;
            uint32_t pb = sb + PA * SA + pl * SB;
            #pragma unroll
            for (int i = tid; i < 512; i += 256) {
                int r = i >> 2, c = i & 3;
                cp16(pb + (r << 6) + ((uint32_t)(c ^ ((r >> 1) & 3)) << 4),
                     src + (size_t)(bn + r) * Kp + k0 + (c << 3));
            }
        }
        cp_commit();
    };

    float acc[MT][4][4];
    #pragma unroll
    for (int i = 0; i < MT; i++)
        #pragma unroll
        for (int j = 0; j < 4; j++)
            #pragma unroll
            for (int q = 0; q < 4; q++) acc[i][j][q] = 0.f;

    const int lrow = (lane & 7) + (((lane >> 3) & 1) << 3);
    const int lchunk = (lane >> 4) & 1;

    load_stage(0, 0);
    if (NKB > 1) load_stage(1, 1);

    for (int kb = 0; kb < NKB; kb++) {
        if (kb < NKB - 1) cp_wait<1>(); else cp_wait<0>();
        __syncthreads();
        if (kb + 2 < NKB) {
            int dst = kb + 2;
            load_stage(dst - (dst / 3) * 3, dst);
        }

        uint32_t sb = sbase + (kb - (kb / 3) * 3) * SSTAGE;
        uint32_t aHb = sb;
        uint32_t aLb = sb + SA;
        uint32_t bHb = sb + PA * SA;
        uint32_t bLb = bHb + SB;

        #pragma unroll
        for (int ks = 0; ks < 2; ks++) {
            uint32_t bH[4][2], bL[4][2];
            #pragma unroll
            for (int nt2 = 0; nt2 < 2; nt2++) {
                int r = wn + (nt2 << 4) + lrow;
                uint32_t c = (uint32_t)((ks << 1) + lchunk);
                uint32_t off = ((uint32_t)r << 6) + (((c ^ ((r >> 1) & 3)) << 4));
                uint32_t r0, r1, r2, r3;
                ldm4(r0, r1, r2, r3, bHb + off);
                bH[2*nt2][0] = r0; bH[2*nt2][1] = r2;
                bH[2*nt2+1][0] = r1; bH[2*nt2+1][1] = r3;
                if (PASSES == 3) {
                    ldm4(r0, r1, r2, r3, bLb + off);
                    bL[2*nt2][0] = r0; bL[2*nt2][1] = r2;
                    bL[2*nt2+1][0] = r1; bL[2*nt2+1][1] = r3;
                }
            }
            #pragma unroll
            for (int mt = 0; mt < MT; mt++) {
                int r = wm + (mt << 4) + lrow;
                uint32_t c = (uint32_t)((ks << 1) + lchunk);
                uint32_t off = ((uint32_t)r << 6) + (((c ^ ((r >> 1) & 3)) << 4));
                uint32_t aH[4], aL[4];
                ldm4(aH[0], aH[1], aH[2], aH[3], aHb + off);
                if (PASSES == 3)
                    ldm4(aL[0], aL[1], aL[2], aL[3], aLb + off);
                // pass-split: each acc touched once per subloop (distance 4)
                #pragma unroll
                for (int nt = 0; nt < 4; nt++)
                    mma16816(acc[mt][nt], aH, bH[nt]);
                if (PASSES == 3) {
                    #pragma unroll
                    for (int nt = 0; nt < 4; nt++)
                        mma16816(acc[mt][nt], aH, bL[nt]);
                    #pragma unroll
                    for (int nt = 0; nt < 4; nt++)
                        mma16816(acc[mt][nt], aL, bH[nt]);
                }
            }
        }
    }

    const int erow = lane >> 2, ecol = (lane & 3) << 1;
    #pragma unroll
    for (int mt = 0; mt < MT; mt++) {
        int r0 = bm + wm + (mt << 4) + erow;
        #pragma unroll
        for (int nt = 0; nt < 4; nt++) {
            int c0 = bn + wn + (nt << 3) + ecol;
            if (OUT == 1) {
                __nv_bfloat162 v0, v1;
                v0.x = __float2bfloat16(acc[mt][nt][0]);
                v0.y = __float2bfloat16(acc[mt][nt][1]);
                v1.x = __float2bfloat16(acc[mt][nt][2]);
                v1.y = __float2bfloat16(acc[mt][nt][3]);
                *(__nv_bfloat162*)(Cb + (size_t)r0 * ldc + c0) = v0;
                *(__nv_bfloat162*)(Cb + (size_t)(r0 + 8) * ldc + c0) = v1;
            } else if (OUT == 2) {
                __half2 v0, v1;
                v0.x = __float2half(acc[mt][nt][0]);
                v0.y = __float2half(acc[mt][nt][1]);
                v1.x = __float2half(acc[mt][nt][2]);
                v1.y = __float2half(acc[mt][nt][3]);
                *(__half2*)(Ch + (size_t)r0 * ldc + c0) = v0;
                *(__half2*)(Ch + (size_t)(r0 + 8) * ldc + c0) = v1;
            } else {
                *(float2*)(Cf + (size_t)r0 * ldc + c0) =
                    make_float2(acc[mt][nt][0], acc[mt][nt][1]);
                *(float2*)(Cf + (size_t)(r0 + 8) * ldc + c0) =
                    make_float2(acc[mt][nt][2], acc[mt][nt][3]);
            }
        }
    }
}

// ------------------------------ shortcut copy -------------------------------
__global__ void copy_kernel(const float4* __restrict__ s, float4* __restrict__ d) {
    int i = blockIdx.x * 256 + threadIdx.x;
    d[i] = s[i];
}

// ------------------------------ LayerNorm + bf16 split ---------------------
__global__ void ln_split_kernel(const float* __restrict__ xin, const float* __restrict__ w,
                                const float* __restrict__ bsh,
                                __nv_bfloat16* __restrict__ oh, __nv_bfloat16* __restrict__ ol) {
    int row = blockIdx.x * 8 + (threadIdx.x >> 5);
    int lane = threadIdx.x & 31;
    const float* r = xin + (size_t)row * Dch;
    float v[24];
    float s = 0.f, s2 = 0.f;
    #pragma unroll
    for (int j = 0; j < 24; j++) { float t = r[lane + j*32]; v[j] = t; s += t; s2 += t*t; }
    #pragma unroll
    for (int o = 16; o; o >>= 1) {
        s  += __shfl_xor_sync(0xFFFFFFFFu, s,  o);
        s2 += __shfl_xor_sync(0xFFFFFFFFu, s2, o);
    }
    float mu = s * (1.f/Dch);
    float rs = rsqrtf(s2 * (1.f/Dch) - mu*mu + 1e-5f);
    #pragma unroll
    for (int j = 0; j < 24; j++) {
        int c = lane + j*32;
        float y = (v[j] - mu) * rs * w[c] + bsh[c];
        __nv_bfloat16 h = __float2bfloat16(y);
        oh[(size_t)row*Dch + c] = h;
        ol[(size_t)row*Dch + c] = __float2bfloat16(y - __bfloat162float(h));
    }
}

// ------------------------------ batched weight hi/lo split -----------------
#define WSEG_BIG   589824
#define WSEG_SMALL 196608
__global__ void wsplit_all_kernel(
    const float* __restrict__ in_proj, const float* __restrict__ outconv,
    const float* __restrict__ outproj, const float* __restrict__ wup,
    const float* __restrict__ lup, const float* __restrict__ uup,
    const float* __restrict__ dcoef,
    __nv_bfloat16* __restrict__ wih, __nv_bfloat16* __restrict__ wil,
    __nv_bfloat16* __restrict__ woh, __nv_bfloat16* __restrict__ wol,
    __nv_bfloat16* __restrict__ wph, __nv_bfloat16* __restrict__ wpl,
    __nv_bfloat16* __restrict__ gwh, __nv_bfloat16* __restrict__ gwl) {
    int idx = blockIdx.x * 256 + threadIdx.x;
    const float* src; __nv_bfloat16 *dh, *dl; int K, Kp, li;
    if (idx < 3 * WSEG_BIG) {
        int seg = idx / WSEG_BIG; li = idx - seg * WSEG_BIG;
        src = (seg == 0) ? in_proj : (seg == 1) ? outconv : outproj;
        dh  = (seg == 0) ? wih : (seg == 1) ? woh : wph;
        dl  = (seg == 0) ? wil : (seg == 1) ? wol : wpl;
        K = Dch; Kp = Dch;
    } else {
        int r = idx - 3 * WSEG_BIG;
        if (r < WSEG_BIG) { src = wup; li = r; dh = gwh; dl = gwl; }
        else {
            r -= WSEG_BIG;
            int seg = r / WSEG_SMALL; li = r - seg * WSEG_SMALL;
            src = (seg == 0) ? lup : (seg == 1) ? uup : dcoef;
            size_t off = (size_t)(3 + seg) * C4 * 64;
            dh = gwh + off; dl = gwl + off;
        }
        K = DS; Kp = 64;
    }
    int m = li / Kp, k = li - m * Kp;
    float v = (k < K) ? src[(size_t)m * K + k] : 0.f;
    __nv_bfloat16 h = __float2bfloat16(v);
    dh[li] = h;
    dl[li] = __float2bfloat16(v - __bfloat162float(h));
}

// ------------------------------ transpose + split (act) --------------------
__global__ void tconv_kernel(const float* __restrict__ src,
                             __nv_bfloat16* __restrict__ dh, __nv_bfloat16* __restrict__ dl) {
    __shared__ float sm[32][33];
    int n0 = blockIdx.x << 5, k0 = blockIdx.y << 5;
    int tx = threadIdx.x, ty = threadIdx.y;
    float v = src[(size_t)(k0 + ty) * NTOT + n0 + tx];
    sm[ty][tx] = v;
    __syncthreads();
    float y = sm[tx][ty];
    __nv_bfloat16 h = __float2bfloat16(y);
    size_t o = (size_t)(n0 + ty) * Dch + k0 + tx;
    dh[o] = h;
    dl[o] = __float2bfloat16(y - __bfloat162float(h));
}

// ------------------------------ xdown + fused remap/split ------------------
__global__ __launch_bounds__(256)
void xdown_kernel(const float* __restrict__ W, const float* __restrict__ X,
                  __nv_bfloat16* __restrict__ dh, __nv_bfloat16* __restrict__ dl) {
    __shared__ float As[8][128];
    __shared__ float Bs[8][64];
    const int M = DS, N = NTOT, K = Dch;
    int bn = blockIdx.x * 64;
    int tid = threadIdx.x;
    int arow = tid >> 1, acol = (tid & 1) * 4;
    int brow = tid >> 5, bcol = tid & 31;
    int tm = (tid >> 4) * 8, tn = (tid & 15) * 4;
    float acc[8][4];
    #pragma unroll
    for (int i = 0; i < 8; i++)
        #pragma unroll
        for (int j = 0; j < 4; j++) acc[i][j] = 0.f;
    for (int k0 = 0; k0 < K; k0 += 8) {
        float4 av = make_float4(0.f,0.f,0.f,0.f);
        if (arow < M)
            av = *(const float4*)(W + (size_t)arow*K + k0 + acol);
        As[acol+0][arow] = av.x; As[acol+1][arow] = av.y;
        As[acol+2][arow] = av.z; As[acol+3][arow] = av.w;
        Bs[brow][bcol]    = X[(size_t)(k0+brow)*N + bn + bcol];
        Bs[brow][bcol+32] = X[(size_t)(k0+brow)*N + bn + bcol + 32];
        __syncthreads();
        #pragma unroll
        for (int kk = 0; kk < 8; kk++) {
            float a[8], bb[4];
            *(float4*)(a)   = *(const float4*)&As[kk][tm];
            *(float4*)(a+4) = *(const float4*)&As[kk][tm+4];
            *(float4*)(bb)  = *(const float4*)&Bs[kk][tn];
            #pragma unroll
            for (int i = 0; i < 8; i++)
                #pragma unroll
                for (int j = 0; j < 4; j++)
                    acc[i][j] = fmaf(a[i], bb[j], acc[i][j]);
        }
        __syncthreads();
    }
    if (tm < 64) {
        #pragma unroll
        for (int i = 0; i < 8; i++) {
            int row = tm + i;
            #pragma unroll
            for (int j = 0; j < 4; j++) {
                int n = bn + tn + j;
                int q = n & 1023;
                int tok = (n & ~1023) + ((q & 31) << 5) + (q >> 5);
                float y = acc[i][j];
                __nv_bfloat16 h = __float2bfloat16(y);
                dh[(size_t)tok*64 + row] = h;
                dl[(size_t)tok*64 + row] = __float2bfloat16(y - __bfloat162float(h));
            }
        }
    }
}

// ------------------------------ dw7: 1x4 strips + fused transpose ----------
__global__ void dw7_kernel(const float* __restrict__ in, const float* __restrict__ wt,
                           const float* __restrict__ bias,
                           float* __restrict__ out, float* __restrict__ outT) {
    int d = blockIdx.x, b = blockIdx.y;
    __shared__ float sm[38][39];
    __shared__ float wsm[49];
    __shared__ float zt[32][33];
    const float* plane = in + (size_t)d*NTOT + b*NPIX;
    int tid = threadIdx.x;
    if (tid < 49) wsm[tid] = wt[d*49 + tid];
    for (int i = tid; i < 38*38; i += 256) {
        int y = i/38, x = i - y*38;
        int yy = y - 3, xx = x - 3;
        sm[y][x] = (yy>=0 && yy<32 && xx>=0 && xx<32) ? plane[yy*32+xx] : 0.f;
    }
    __syncthreads();
    float bv = bias[d];
    int y  = tid >> 3;
    int x0 = (tid & 7) << 2;
    float a0 = bv, a1 = bv, a2 = bv, a3 = bv;
    #pragma unroll
    for (int ky = 0; ky < 7; ky++) {
        float r[10];
        #pragma unroll
        for (int i = 0; i < 10; i++) r[i] = sm[y+ky][x0+i];
        #pragma unroll
        for (int kx = 0; kx < 7; kx++) {
            float wv = wsm[ky*7+kx];
            a0 = fmaf(r[kx],   wv, a0);
            a1 = fmaf(r[kx+1], wv, a1);
            a2 = fmaf(r[kx+2], wv, a2);
            a3 = fmaf(r[kx+3], wv, a3);
        }
    }
    size_t base = (size_t)d*NTOT + b*NPIX;
    *(float4*)(out + base + (y << 5) + x0) = make_float4(a0, a1, a2, a3);
    zt[y][x0] = a0; zt[y][x0+1] = a1; zt[y][x0+2] = a2; zt[y][x0+3] = a3;
    __syncthreads();
    float4 vt = make_float4(zt[x0][y], zt[x0+1][y], zt[x0+2][y], zt[x0+3][y]);
    *(float4*)(outT + base + (y << 5) + x0) = vt;
}

// ------------------------------ dw3 + y*relu(y): 1x4 strips ----------------
__global__ void dw3act_kernel(const float* __restrict__ in, const float* __restrict__ wt,
                              float* __restrict__ out) {
    int d = blockIdx.x, b = blockIdx.y;
    __shared__ float sm[34][35];
    __shared__ float wsm[9];
    const float* plane = in + (size_t)d*NTOT + b*NPIX;
    int tid = threadIdx.x;
    if (tid < 9) wsm[tid] = wt[d*9 + tid];
    for (int i = tid; i < 34*34; i += 256) {
        int y = i/34, x = i - y*34;
        int yy = y - 1, xx = x - 1;
        sm[y][x] = (yy>=0 && yy<32 && xx>=0 && xx<32) ? plane[yy*32+xx] : 0.f;
    }
    __syncthreads();
    int y  = tid >> 3;
    int x0 = (tid & 7) << 2;
    float a0 = 0.f, a1 = 0.f, a2 = 0.f, a3 = 0.f;
    #pragma unroll
    for (int ky = 0; ky < 3; ky++) {
        float r[6];
        #pragma unroll
        for (int i = 0; i < 6; i++) r[i] = sm[y+ky][x0+i];
        #pragma unroll
        for (int kx = 0; kx < 3; kx++) {
            float wv = wsm[ky*3+kx];
            a0 = fmaf(r[kx],   wv, a0);
            a1 = fmaf(r[kx+1], wv, a1);
            a2 = fmaf(r[kx+2], wv, a2);
            a3 = fmaf(r[kx+3], wv, a3);
        }
    }
    float z0 = (a0 > 0.f) ? a0*a0 : 0.f;
    float z1 = (a1 > 0.f) ? a1*a1 : 0.f;
    float z2 = (a2 > 0.f) ? a2*a2 : 0.f;
    float z3 = (a3 > 0.f) ? a3*a3 : 0.f;
    *(float4*)(out + (size_t)d*NTOT + b*NPIX + (y << 5) + x0) =
        make_float4(z0, z1, z2, z3);
}

// ------------------------------ scan ---------------------------------------
__global__ void scan_kernel(const __nv_bfloat16* __restrict__ gsig,
                            const __half* __restrict__ glud,
                            const float* __restrict__ x2,
                            const float* __restrict__ x2t,
                            const float* __restrict__ mw,
                            __half* __restrict__ s4) {
    int c4 = blockIdx.x, b = blockIdx.y;
    int k = c4 / Dch, d = c4 - k*Dch;
    int tid = threadIdx.x;
    int chunk = tid >> 5, h = tid & 31;
    const size_t PS = (size_t)C4 * NTOT;
    const __nv_bfloat16* Gl = gsig + (size_t)c4*NTOT + (size_t)b*NPIX;
    const __nv_bfloat16* Gm = Gl + PS;
    const __nv_bfloat16* Gr = Gl + 2*PS;
    const __half* Lp = glud + (size_t)c4*NTOT + (size_t)b*NPIX;
    const __half* Up = Lp + PS;
    const __half* Dp = Lp + 2*PS;
    const float* xsrc = ((k & 1) ? x2 : x2t) + (size_t)d*NTOT + b*NPIX;
    float mk = mw[k];
    __half* outp = s4 + (size_t)c4*NTOT + b*NPIX;
    float hs = 0.f;
    const unsigned mask = 0xFFFFFFFFu;
    #pragma unroll
    for (int pos = 0; pos < 8; pos++) {
        int w  = chunk*8 + pos;
        int q  = w*32 + h;
        int wq = (k >= 2) ? (31 - w) : w;
        float xv = xsrc[wq*32 + h];
        float a  = __bfloat162float(Gl[q]);
        float bb = __bfloat162float(Gm[q]);
        float cc = __bfloat162float(Gr[q]);
        float l  = __half2float(Lp[q]);
        float ea = fast_exp(a), eb = fast_exp(bb), ec = fast_exp(cc);
        float qa = 1.f + ea, qb = 1.f + eb, qc = 1.f + ec;
        float pl = ea*qb*qc, pm = eb*qa*qc, pr = ec*qa*qb;
        float den = pl + pm + pr;
        if (h == 0)  den = pm + pr;
        if (h == 31) den = pl + pm;
        float rd = fast_rcp(den);
        float gl = pl*rd, gm = pm*rd, gr = pr*rd;
        float up = __shfl_up_sync(mask, hs, 1);
        float dn = __shfl_down_sync(mask, hs, 1);
        if (h == 0)  up = 0.f;
        if (h == 31) dn = 0.f;
        hs = fmaf(l, xv, fmaf(gl, up, fmaf(gm, hs, gr*dn)));
        float uv = __half2float(Up[q]), dv = __half2float(Dp[q]);
        outp[q] = __float2half(mk * fmaf(hs, uv, xv*dv));
    }
}

// ------------------------------ merge + transpose + bf16 split -------------
__global__ void merge_split_kernel(const __half* __restrict__ s4,
                                   __nv_bfloat16* __restrict__ dh,
                                   __nv_bfloat16* __restrict__ dl) {
    __shared__ float sm[32][33];
    int d0 = blockIdx.x << 5, b = blockIdx.y;
    int tx = threadIdx.x, ty = threadIdx.y;
    for (int pg = blockIdx.z * 8; pg < blockIdx.z * 8 + 8; pg++) {
        int q = (pg << 5) + tx;
        float v = 0.f;
        #pragma unroll
        for (int k = 0; k < 4; k++)
            v += __half2float(s4[(size_t)(k*Dch + d0 + ty)*NTOT + b*NPIX + q]);
        sm[ty][tx] = v;
        __syncthreads();
        float y = sm[tx][ty];
        __nv_bfloat16 hh = __float2bfloat16(y);
        size_t o = (size_t)(b*NPIX + (ty << 5) + pg) * Dch + d0 + tx;
        dh[o] = hh;
        dl[o] = __float2bfloat16(y - __bfloat162float(hh));
        __syncthreads();
    }
}

// ------------------------------ launch -------------------------------------
extern "C" void kernel_launch(void* const* d_in, const int* in_sizes, int n_in,
                              void* d_out, int out_size) {
    const float* hidden   = (const float*)d_in[0];
    const float* norm_w   = (const float*)d_in[1];
    const float* norm_b   = (const float*)d_in[2];
    const float* in_proj  = (const float*)d_in[3];
    const float* conv7_w  = (const float*)d_in[4];
    const float* conv7_b  = (const float*)d_in[5];
    const float* xdown_w  = (const float*)d_in[6];
    const float* wup_w    = (const float*)d_in[7];
    const float* lup_w    = (const float*)d_in[8];
    const float* uup_w    = (const float*)d_in[9];
    const float* dcoef_w  = (const float*)d_in[10];
    const float* m_w      = (const float*)d_in[11];
    const float* outconv_w  = (const float*)d_in[12];
    const float* outdconv_w = (const float*)d_in[13];
    const float* outproj_w  = (const float*)d_in[14];
    float* outp = (float*)d_out;

    float *x1,*x2,*x2t,*oc,*act;
    __half *glud,*s4;
    __nv_bfloat16 *gsig,*xlnh,*xlnl,*wih,*wil,*woh,*wol,*wph,*wpl,*gwh,*gwl,
                  *xpnh,*xpnl,*mnh,*mnl,*anh,*anl;
    cudaGetSymbolAddress((void**)&x1, g_x1);   cudaGetSymbolAddress((void**)&x2, g_x2);
    cudaGetSymbolAddress((void**)&x2t,g_x2t);
    cudaGetSymbolAddress((void**)&gsig,g_gsig);cudaGetSymbolAddress((void**)&glud,g_glud);
    cudaGetSymbolAddress((void**)&s4, g_s4);   cudaGetSymbolAddress((void**)&oc, g_oc);
    cudaGetSymbolAddress((void**)&act,g_act);
    cudaGetSymbolAddress((void**)&xlnh,g_xlnh);cudaGetSymbolAddress((void**)&xlnl,g_xlnl);
    cudaGetSymbolAddress((void**)&wih,g_wih);  cudaGetSymbolAddress((void**)&wil,g_wil);
    cudaGetSymbolAddress((void**)&woh,g_woh);  cudaGetSymbolAddress((void**)&wol,g_wol);
    cudaGetSymbolAddress((void**)&wph,g_wph);  cudaGetSymbolAddress((void**)&wpl,g_wpl);
    cudaGetSymbolAddress((void**)&gwh,g_gwh);  cudaGetSymbolAddress((void**)&gwl,g_gwl);
    cudaGetSymbolAddress((void**)&xpnh,g_xpnh);cudaGetSymbolAddress((void**)&xpnl,g_xpnl);
    cudaGetSymbolAddress((void**)&mnh,g_mnh);  cudaGetSymbolAddress((void**)&mnl,g_mnl);
    cudaGetSymbolAddress((void**)&anh,g_anh);  cudaGetSymbolAddress((void**)&anl,g_anl);

    const int SMEM_TM64_3 = 3 * 24576;   // 72KB, 3-pass TM=64
    const int SMEM_TM64_1 = 3 * 12288;   // 36KB, 1-pass TM=64
    cudaFuncSetAttribute(mma_gemm<3,0,64,3>, cudaFuncAttributeMaxDynamicSharedMemorySize, SMEM_TM64_3);
    cudaFuncSetAttribute(mma_gemm<3,2,64,3>, cudaFuncAttributeMaxDynamicSharedMemorySize, SMEM_TM64_3);
    cudaFuncSetAttribute(mma_gemm<1,1,64,3>, cudaFuncAttributeMaxDynamicSharedMemorySize, SMEM_TM64_1);
    dim3 b3232(32, 32);

    // 1) batched weight splits
    wsplit_all_kernel<<<(4*WSEG_BIG + 3*WSEG_SMALL)/256, 256>>>(
        in_proj, outconv_w, outproj_w, wup_w, lup_w, uup_w, dcoef_w,
        wih, wil, woh, wol, wph, wpl, gwh, gwl);

    // 2) LN -> bf16 hi/lo
    ln_split_kernel<<<NTOT/8, 256>>>(hidden, norm_w, norm_b, xlnh, xlnl);

    // 3) shortcut copy (keeps in_proj as profiled launch #4)
    copy_kernel<<<BTD/1024, 256>>>((const float4*)hidden, (float4*)(outp + BTD));

    // 4) in_proj (TM=64, grid 384)
    mma_gemm<3,0,64,3><<<dim3(NTOT/128, Dch/64), 256, SMEM_TM64_3>>>(
        wih, wil, xlnh, xlnl, x1, nullptr, nullptr, Dch, NTOT);

    // 5) dw 7x7 (+ fused w-major transpose)
    dw7_kernel<<<dim3(Dch, Bsz), 256>>>(x1, conv7_w, conv7_b, x2, x2t);

    // 6) xdown + fused remap/split -> xpn hi/lo
    xdown_kernel<<<dim3(NTOT/64, 1), 256>>>(xdown_w, x2, xpnh, xpnl);

    // 7) sigmoid gates: 1-pass bf16 out (TM=64, grid 4608)
    mma_gemm<1,1,64,3><<<dim3(NTOT/128, (3*C4)/64), 256, SMEM_TM64_1>>>(
        gwh, nullptr, xpnh, nullptr, nullptr, gsig, nullptr, 64, NTOT);

    // 8) L|U|D: 3-pass, fp16 storage out (TM=64, grid 4608)
    mma_gemm<3,2,64,3><<<dim3(NTOT/128, (3*C4)/64), 256, SMEM_TM64_3>>>(
        gwh + (size_t)3*C4*64, gwl + (size_t)3*C4*64, xpnh, xpnl,
        nullptr, nullptr, glud, 64, NTOT);

    // 9) scan
    scan_kernel<<<dim3(C4, Bsz), 128>>>(gsig, glud, x2, x2t, m_w, s4);

    // 10) merge + transpose + split -> mn hi/lo
    merge_split_kernel<<<dim3(Dch/32, Bsz, 4), b3232>>>(s4, mnh, mnl);

    // 11) outconv (TM=64, grid 384)
    mma_gemm<3,0,64,3><<<dim3(NTOT/128, Dch/64), 256, SMEM_TM64_3>>>(
        woh, wol, mnh, mnl, oc, nullptr, nullptr, Dch, NTOT);

    // 12) dw 3x3 + y*relu(y)
    dw3act_kernel<<<dim3(Dch, Bsz), 256>>>(oc, outdconv_w, act);

    // 13) act -> (4096x768) hi/lo
    tconv_kernel<<<dim3(NTOT/32, Dch/32), b3232>>>(act, anh, anl);

    // 14) outproj -> d_out (TM=64, grid 384)
    mma_gemm<3,0,64,3><<<dim3(Dch/128, NTOT/64), 256, SMEM_TM64_3>>>(
        anh, anl, wph, wpl, outp, nullptr, nullptr, Dch, Dch);
}

// round 13
// speedup vs baseline: 1.0441x; 1.0441x over previous
#include <cuda_runtime.h>
#include <cuda_bf16.h>
#include <cuda_fp16.h>
#include <cstdint>

// ---------------------------------------------------------------------------
// GSPN block. B=4, T=1024, D=768, HW=32, DS=48, CHUNK=8.
// Round 13: BISECT — in_proj only on fp16 2-pass GEMM (hardcoded variant);
// everything else identical to round 12 (473 us baseline).
// ---------------------------------------------------------------------------

#define Bsz   4
#define Dch   768
#define Tlen  1024
#define DS    48
#define NPIX  1024
#define NTOT  4096
#define C4    (4*Dch)         // 3072
#define MG    (6*C4)          // 18432
#define BTD   (Bsz*Tlen*Dch)

// ------------------------- static scratch ----------------------------------
__device__ float g_x1 [(size_t)Dch*NTOT];
__device__ float g_x2 [(size_t)Dch*NTOT];
__device__ float g_x2t[(size_t)Dch*NTOT];
__device__ __nv_bfloat16 g_gsig[(size_t)3*C4*NTOT];
__device__ __align__(16) __half g_glud[(size_t)3*C4*NTOT];
__device__ __align__(16) __half g_s4 [(size_t)C4*NTOT];
__device__ float g_oc [(size_t)Dch*NTOT];
__device__ float g_act[(size_t)Dch*NTOT];

__device__ __align__(16) __half g_xlnf[(size_t)NTOT*Dch];          // fp16 (in_proj B)
__device__ __align__(16) __half g_wihf[Dch*Dch], g_wilf[Dch*Dch];  // fp16 hi/lo Wi
__device__ __align__(16) __nv_bfloat16 g_woh [Dch*Dch], g_wol [Dch*Dch];
__device__ __align__(16) __nv_bfloat16 g_wph [Dch*Dch], g_wpl [Dch*Dch];
__device__ __align__(16) __nv_bfloat16 g_gwh [(size_t)MG*64], g_gwl [(size_t)MG*64];
__device__ __align__(16) __nv_bfloat16 g_xpnh[(size_t)NTOT*64], g_xpnl[(size_t)NTOT*64];
__device__ __align__(16) __nv_bfloat16 g_mnh [(size_t)NTOT*Dch], g_mnl [(size_t)NTOT*Dch];
__device__ __align__(16) __nv_bfloat16 g_anh [(size_t)NTOT*Dch], g_anl [(size_t)NTOT*Dch];

// ------------------------------ helpers ------------------------------------
__device__ __forceinline__ uint32_t smem_u32(const void* p) {
    uint32_t r;
    asm("{ .reg .u64 t; cvta.to.shared.u64 t, %1; cvt.u32.u64 %0, t; }"
        : "=r"(r) : "l"(p));
    return r;
}
__device__ __forceinline__ void cp16(uint32_t saddr, const void* gptr) {
    asm volatile("cp.async.cg.shared.global [%0], [%1], 16;"
        :: "r"(saddr), "l"(gptr));
}
__device__ __forceinline__ void cp_commit() {
    asm volatile("cp.async.commit_group;" ::: "memory");
}
template<int N>
__device__ __forceinline__ void cp_wait() {
    asm volatile("cp.async.wait_group %0;" :: "n"(N) : "memory");
}
__device__ __forceinline__ void ldm4(uint32_t& r0, uint32_t& r1, uint32_t& r2,
                                     uint32_t& r3, uint32_t addr) {
    asm volatile("ldmatrix.sync.aligned.m8n8.x4.shared.b16 {%0,%1,%2,%3}, [%4];"
        : "=r"(r0), "=r"(r1), "=r"(r2), "=r"(r3) : "r"(addr));
}
__device__ __forceinline__ void mma16816(float* c, const uint32_t* a,
                                         const uint32_t* b) {
    asm volatile("mma.sync.aligned.m16n8k16.row.col.f32.bf16.bf16.f32 "
        "{%0,%1,%2,%3}, {%4,%5,%6,%7}, {%8,%9}, {%0,%1,%2,%3};"
        : "+f"(c[0]), "+f"(c[1]), "+f"(c[2]), "+f"(c[3])
        : "r"(a[0]), "r"(a[1]), "r"(a[2]), "r"(a[3]), "r"(b[0]), "r"(b[1]));
}
__device__ __forceinline__ void mma16816h(float* c, const uint32_t* a,
                                          const uint32_t* b) {
    asm volatile("mma.sync.aligned.m16n8k16.row.col.f32.f16.f16.f32 "
        "{%0,%1,%2,%3}, {%4,%5,%6,%7}, {%8,%9}, {%0,%1,%2,%3};"
        : "+f"(c[0]), "+f"(c[1]), "+f"(c[2]), "+f"(c[3])
        : "r"(a[0]), "r"(a[1]), "r"(a[2]), "r"(a[3]), "r"(b[0]), "r"(b[1]));
}

__device__ __forceinline__ float fast_exp(float x) {
    x = fminf(fmaxf(x, -20.f), 20.f);
    float t = x * 1.4426950408889634f;
    float r = t + 12582912.f;
    int   i = __float_as_int(r) - 0x4B400000;
    float f = t - (r - 12582912.f);
    const float c1=0.69314718056f, c2=0.2402265069f, c3=0.0555041087f,
                c4=0.00961812911f, c5=0.00133335581f;
    float p = fmaf(c5, f, c4);
    p = fmaf(p, f, c3); p = fmaf(p, f, c2); p = fmaf(p, f, c1); p = fmaf(p, f, 1.f);
    return __int_as_float(__float_as_int(p) + (i << 23));
}
__device__ __forceinline__ float fast_rcp(float x) {
    float y = __int_as_float(0x7EF311C3 - __float_as_int(x));
    y = y * (2.0f - x * y);
    y = y * (2.0f - x * y);
    y = y * (2.0f - x * y);
    return y;
}

// ------------------------------ HMMA GEMM (bf16, proven) --------------------
template<int PASSES, int OUT, int TM, int MAXCTA>
__global__ __launch_bounds__(256, MAXCTA)
void mma_gemm(const __nv_bfloat16* __restrict__ Ahi, const __nv_bfloat16* __restrict__ Alo,
              const __nv_bfloat16* __restrict__ Bhi, const __nv_bfloat16* __restrict__ Blo,
              float* __restrict__ Cf, __nv_bfloat16* __restrict__ Cb,
              __half* __restrict__ Ch, int Kp, int ldc) {
    extern __shared__ __align__(16) char dsm[];
    const int PA = (PASSES == 3) ? 2 : 1;
    const int SA = TM * 64;
    const int SB = 8192;
    const int SSTAGE = PA * SA + PA * SB;
    const int MT = TM / 32;
    const int tid  = threadIdx.x;
    const int wid  = tid >> 5, lane = tid & 31;
    const int wm   = (wid >> 2) * (TM >> 1);
    const int wn   = (wid & 3)  << 5;
    const int bm   = blockIdx.y * TM, bn = blockIdx.x << 7;
    const uint32_t sbase = smem_u32(dsm);
    const int NKB = Kp >> 5;

    auto load_stage = [&](int buf, int kb) {
        const int k0 = kb << 5;
        uint32_t sb = sbase + buf * SSTAGE;
        #pragma unroll
        for (int pl = 0; pl < PA; pl++) {
            const __nv_bfloat16* src = (pl == 0) ? Ahi : Alo;
            uint32_t pb = sb + pl * SA;
            #pragma unroll
            for (int i = tid; i < TM * 4; i += 256) {
                int r = i >> 2, c = i & 3;
                cp16(pb + (r << 6) + ((uint32_t)(c ^ ((r >> 1) & 3)) << 4),
                     src + (size_t)(bm + r) * Kp + k0 + (c << 3));
            }
        }
        #pragma unroll
        for (int pl = 0; pl < PA; pl++) {
            const __nv_bfloat16* src = (pl == 0) ? Bhi : Blo;
            uint32_t pb = sb + PA * SA + pl * SB;
            #pragma unroll
            for (int i = tid; i < 512; i += 256) {
                int r = i >> 2, c = i & 3;
                cp16(pb + (r << 6) + ((uint32_t)(c ^ ((r >> 1) & 3)) << 4),
                     src + (size_t)(bn + r) * Kp + k0 + (c << 3));
            }
        }
        cp_commit();
    };

    float acc[MT][4][4];
    #pragma unroll
    for (int i = 0; i < MT; i++)
        #pragma unroll
        for (int j = 0; j < 4; j++)
            #pragma unroll
            for (int q = 0; q < 4; q++) acc[i][j][q] = 0.f;

    const int lrow = (lane & 7) + (((lane >> 3) & 1) << 3);
    const int lchunk = (lane >> 4) & 1;

    load_stage(0, 0);
    if (NKB > 1) load_stage(1, 1);

    for (int kb = 0; kb < NKB; kb++) {
        if (kb < NKB - 1) cp_wait<1>(); else cp_wait<0>();
        __syncthreads();
        if (kb + 2 < NKB) {
            int dst = kb + 2;
            load_stage(dst - (dst / 3) * 3, dst);
        }

        uint32_t sb = sbase + (kb - (kb / 3) * 3) * SSTAGE;
        uint32_t aHb = sb;
        uint32_t aLb = sb + SA;
        uint32_t bHb = sb + PA * SA;
        uint32_t bLb = bHb + SB;

        #pragma unroll
        for (int ks = 0; ks < 2; ks++) {
            uint32_t bH[4][2], bL[4][2];
            #pragma unroll
            for (int nt2 = 0; nt2 < 2; nt2++) {
                int r = wn + (nt2 << 4) + lrow;
                uint32_t c = (uint32_t)((ks << 1) + lchunk);
                uint32_t off = ((uint32_t)r << 6) + (((c ^ ((r >> 1) & 3)) << 4));
                uint32_t r0, r1, r2, r3;
                ldm4(r0, r1, r2, r3, bHb + off);
                bH[2*nt2][0] = r0; bH[2*nt2][1] = r2;
                bH[2*nt2+1][0] = r1; bH[2*nt2+1][1] = r3;
                if (PASSES == 3) {
                    ldm4(r0, r1, r2, r3, bLb + off);
                    bL[2*nt2][0] = r0; bL[2*nt2][1] = r2;
                    bL[2*nt2+1][0] = r1; bL[2*nt2+1][1] = r3;
                }
            }
            #pragma unroll
            for (int mt = 0; mt < MT; mt++) {
                int r = wm + (mt << 4) + lrow;
                uint32_t c = (uint32_t)((ks << 1) + lchunk);
                uint32_t off = ((uint32_t)r << 6) + (((c ^ ((r >> 1) & 3)) << 4));
                uint32_t aH[4], aL[4];
                ldm4(aH[0], aH[1], aH[2], aH[3], aHb + off);
                if (PASSES == 3)
                    ldm4(aL[0], aL[1], aL[2], aL[3], aLb + off);
                #pragma unroll
                for (int nt = 0; nt < 4; nt++)
                    mma16816(acc[mt][nt], aH, bH[nt]);
                if (PASSES == 3) {
                    #pragma unroll
                    for (int nt = 0; nt < 4; nt++)
                        mma16816(acc[mt][nt], aH, bL[nt]);
                    #pragma unroll
                    for (int nt = 0; nt < 4; nt++)
                        mma16816(acc[mt][nt], aL, bH[nt]);
                }
            }
        }
    }

    const int erow = lane >> 2, ecol = (lane & 3) << 1;
    #pragma unroll
    for (int mt = 0; mt < MT; mt++) {
        int r0 = bm + wm + (mt << 4) + erow;
        #pragma unroll
        for (int nt = 0; nt < 4; nt++) {
            int c0 = bn + wn + (nt << 3) + ecol;
            if (OUT == 1) {
                __nv_bfloat162 v0, v1;
                v0.x = __float2bfloat16(acc[mt][nt][0]);
                v0.y = __float2bfloat16(acc[mt][nt][1]);
                v1.x = __float2bfloat16(acc[mt][nt][2]);
                v1.y = __float2bfloat16(acc[mt][nt][3]);
                *(__nv_bfloat162*)(Cb + (size_t)r0 * ldc + c0) = v0;
                *(__nv_bfloat162*)(Cb + (size_t)(r0 + 8) * ldc + c0) = v1;
            } else if (OUT == 2) {
                __half2 v0, v1;
                v0.x = __float2half(acc[mt][nt][0]);
                v0.y = __float2half(acc[mt][nt][1]);
                v1.x = __float2half(acc[mt][nt][2]);
                v1.y = __float2half(acc[mt][nt][3]);
                *(__half2*)(Ch + (size_t)r0 * ldc + c0) = v0;
                *(__half2*)(Ch + (size_t)(r0 + 8) * ldc + c0) = v1;
            } else {
                *(float2*)(Cf + (size_t)r0 * ldc + c0) =
                    make_float2(acc[mt][nt][0], acc[mt][nt][1]);
                *(float2*)(Cf + (size_t)(r0 + 8) * ldc + c0) =
                    make_float2(acc[mt][nt][2], acc[mt][nt][3]);
            }
        }
    }
}

// ------------------------------ fp16 2-pass GEMM (A hi/lo, B single) --------
// C(MxN fp32) = (Ahi+Alo)(Mx Kp) @ B(NxKp)^T. TM=64, 8 warps, BK=32, 3 stages.
// Hardcoded plane layout: [Ahi | Alo | B] per stage (4K+4K+8K = 16KB).
__global__ __launch_bounds__(256, 3)
void mma_gemm_f16(const __half* __restrict__ Ahi, const __half* __restrict__ Alo,
                  const __half* __restrict__ B,
                  float* __restrict__ Cf, int Kp, int ldc) {
    extern __shared__ __align__(16) char dsm[];
    const int SA = 64 * 64;          // 4096
    const int SSTAGE = 2 * SA + 8192;
    const int tid  = threadIdx.x;
    const int wid  = tid >> 5, lane = tid & 31;
    const int wm   = (wid >> 2) << 5;       // 0 / 32
    const int wn   = (wid & 3)  << 5;
    const int bm   = blockIdx.y << 6, bn = blockIdx.x << 7;
    const uint32_t sbase = smem_u32(dsm);
    const int NKB = Kp >> 5;

    auto load_stage = [&](int buf, int kb) {
        const int k0 = kb << 5;
        uint32_t sb = sbase + buf * SSTAGE;
        #pragma unroll
        for (int pl = 0; pl < 2; pl++) {
            const __half* src = (pl == 0) ? Ahi : Alo;
            uint32_t pb = sb + pl * SA;
            { // 256 chunks, 1/thread
                int r = tid >> 2, c = tid & 3;
                cp16(pb + (r << 6) + ((uint32_t)(c ^ ((r >> 1) & 3)) << 4),
                     src + (size_t)(bm + r) * Kp + k0 + (c << 3));
            }
        }
        {
            uint32_t pb = sb + 2 * SA;
            #pragma unroll
            for (int i = tid; i < 512; i += 256) {
                int r = i >> 2, c = i & 3;
                cp16(pb + (r << 6) + ((uint32_t)(c ^ ((r >> 1) & 3)) << 4),
                     B + (size_t)(bn + r) * Kp + k0 + (c << 3));
            }
        }
        cp_commit();
    };

    float acc[2][4][4];
    #pragma unroll
    for (int i = 0; i < 2; i++)
        #pragma unroll
        for (int j = 0; j < 4; j++)
            #pragma unroll
            for (int q = 0; q < 4; q++) acc[i][j][q] = 0.f;

    const int lrow = (lane & 7) + (((lane >> 3) & 1) << 3);
    const int lchunk = (lane >> 4) & 1;

    load_stage(0, 0);
    if (NKB > 1) load_stage(1, 1);

    for (int kb = 0; kb < NKB; kb++) {
        if (kb < NKB - 1) cp_wait<1>(); else cp_wait<0>();
        __syncthreads();
        if (kb + 2 < NKB) {
            int dst = kb + 2;
            load_stage(dst - (dst / 3) * 3, dst);
        }

        uint32_t sb = sbase + (kb - (kb / 3) * 3) * SSTAGE;
        uint32_t aHb = sb, aLb = sb + SA, bHb = sb + 2 * SA;

        #pragma unroll
        for (int ks = 0; ks < 2; ks++) {
            uint32_t bH[4][2];
            #pragma unroll
            for (int nt2 = 0; nt2 < 2; nt2++) {
                int r = wn + (nt2 << 4) + lrow;
                uint32_t c = (uint32_t)((ks << 1) + lchunk);
                uint32_t off = ((uint32_t)r << 6) + (((c ^ ((r >> 1) & 3)) << 4));
                uint32_t r0, r1, r2, r3;
                ldm4(r0, r1, r2, r3, bHb + off);
                bH[2*nt2][0] = r0; bH[2*nt2][1] = r2;
                bH[2*nt2+1][0] = r1; bH[2*nt2+1][1] = r3;
            }
            #pragma unroll
            for (int mt = 0; mt < 2; mt++) {
                int r = wm + (mt << 4) + lrow;
                uint32_t c = (uint32_t)((ks << 1) + lchunk);
                uint32_t off = ((uint32_t)r << 6) + (((c ^ ((r >> 1) & 3)) << 4));
                uint32_t aH[4], aL[4];
                ldm4(aH[0], aH[1], aH[2], aH[3], aHb + off);
                ldm4(aL[0], aL[1], aL[2], aL[3], aLb + off);
                #pragma unroll
                for (int nt = 0; nt < 4; nt++)
                    mma16816h(acc[mt][nt], aH, bH[nt]);
                #pragma unroll
                for (int nt = 0; nt < 4; nt++)
                    mma16816h(acc[mt][nt], aL, bH[nt]);
            }
        }
    }

    const int erow = lane >> 2, ecol = (lane & 3) << 1;
    #pragma unroll
    for (int mt = 0; mt < 2; mt++) {
        int r0 = bm + wm + (mt << 4) + erow;
        #pragma unroll
        for (int nt = 0; nt < 4; nt++) {
            int c0 = bn + wn + (nt << 3) + ecol;
            *(float2*)(Cf + (size_t)r0 * ldc + c0) =
                make_float2(acc[mt][nt][0], acc[mt][nt][1]);
            *(float2*)(Cf + (size_t)(r0 + 8) * ldc + c0) =
                make_float2(acc[mt][nt][2], acc[mt][nt][3]);
        }
    }
}

// ------------------------------ shortcut copy -------------------------------
__global__ void copy_kernel(const float4* __restrict__ s, float4* __restrict__ d) {
    int i = blockIdx.x * 256 + threadIdx.x;
    d[i] = s[i];
}

// ------------------------------ LayerNorm -> fp16 single --------------------
__global__ void ln_half_kernel(const float* __restrict__ xin, const float* __restrict__ w,
                               const float* __restrict__ bsh,
                               __half* __restrict__ oh) {
    int row = blockIdx.x * 8 + (threadIdx.x >> 5);
    int lane = threadIdx.x & 31;
    const float* r = xin + (size_t)row * Dch;
    float v[24];
    float s = 0.f, s2 = 0.f;
    #pragma unroll
    for (int j = 0; j < 24; j++) { float t = r[lane + j*32]; v[j] = t; s += t; s2 += t*t; }
    #pragma unroll
    for (int o = 16; o; o >>= 1) {
        s  += __shfl_xor_sync(0xFFFFFFFFu, s,  o);
        s2 += __shfl_xor_sync(0xFFFFFFFFu, s2, o);
    }
    float mu = s * (1.f/Dch);
    float rs = rsqrtf(s2 * (1.f/Dch) - mu*mu + 1e-5f);
    #pragma unroll
    for (int j = 0; j < 24; j++) {
        int c = lane + j*32;
        float y = (v[j] - mu) * rs * w[c] + bsh[c];
        oh[(size_t)row*Dch + c] = __float2half(y);
    }
}

// ------------------------------ in_proj weight fp16 hi/lo split -------------
__global__ void wsplit_f16_kernel(const float* __restrict__ src,
                                  __half* __restrict__ dh, __half* __restrict__ dl) {
    int idx = blockIdx.x * 256 + threadIdx.x;   // 0..589823
    float v = src[idx];
    __half h = __float2half(v);
    dh[idx] = h;
    dl[idx] = __float2half(v - __half2float(h));
}

// ------------------------------ batched weight hi/lo split (bf16, rest) ----
#define WSEG_BIG   589824
#define WSEG_SMALL 196608
__global__ void wsplit_all_kernel(
    const float* __restrict__ outconv,
    const float* __restrict__ outproj, const float* __restrict__ wup,
    const float* __restrict__ lup, const float* __restrict__ uup,
    const float* __restrict__ dcoef,
    __nv_bfloat16* __restrict__ woh, __nv_bfloat16* __restrict__ wol,
    __nv_bfloat16* __restrict__ wph, __nv_bfloat16* __restrict__ wpl,
    __nv_bfloat16* __restrict__ gwh, __nv_bfloat16* __restrict__ gwl) {
    int idx = blockIdx.x * 256 + threadIdx.x;
    const float* src; __nv_bfloat16 *dh, *dl; int K, Kp, li;
    if (idx < 2 * WSEG_BIG) {
        int seg = idx / WSEG_BIG; li = idx - seg * WSEG_BIG;
        src = (seg == 0) ? outconv : outproj;
        dh  = (seg == 0) ? woh : wph;
        dl  = (seg == 0) ? wol : wpl;
        K = Dch; Kp = Dch;
    } else {
        int r = idx - 2 * WSEG_BIG;
        if (r < WSEG_BIG) { src = wup; li = r; dh = gwh; dl = gwl; }
        else {
            r -= WSEG_BIG;
            int seg = r / WSEG_SMALL; li = r - seg * WSEG_SMALL;
            src = (seg == 0) ? lup : (seg == 1) ? uup : dcoef;
            size_t off = (size_t)(3 + seg) * C4 * 64;
            dh = gwh + off; dl = gwl + off;
        }
        K = DS; Kp = 64;
    }
    int m = li / Kp, k = li - m * Kp;
    float v = (k < K) ? src[(size_t)m * K + k] : 0.f;
    __nv_bfloat16 h = __float2bfloat16(v);
    dh[li] = h;
    dl[li] = __float2bfloat16(v - __bfloat162float(h));
}

// ------------------------------ transpose + split (act) --------------------
__global__ void tconv_kernel(const float* __restrict__ src,
                             __nv_bfloat16* __restrict__ dh, __nv_bfloat16* __restrict__ dl) {
    __shared__ float sm[32][33];
    int n0 = blockIdx.x << 5, k0 = blockIdx.y << 5;
    int tx = threadIdx.x, ty = threadIdx.y;
    float v = src[(size_t)(k0 + ty) * NTOT + n0 + tx];
    sm[ty][tx] = v;
    __syncthreads();
    float y = sm[tx][ty];
    __nv_bfloat16 h = __float2bfloat16(y);
    size_t o = (size_t)(n0 + ty) * Dch + k0 + tx;
    dh[o] = h;
    dl[o] = __float2bfloat16(y - __bfloat162float(h));
}

// ------------------------------ xdown + fused remap/split ------------------
__global__ __launch_bounds__(256)
void xdown_kernel(const float* __restrict__ W, const float* __restrict__ X,
                  __nv_bfloat16* __restrict__ dh, __nv_bfloat16* __restrict__ dl) {
    __shared__ float As[8][128];
    __shared__ float Bs[8][64];
    const int M = DS, N = NTOT, K = Dch;
    int bn = blockIdx.x * 64;
    int tid = threadIdx.x;
    int arow = tid >> 1, acol = (tid & 1) * 4;
    int brow = tid >> 5, bcol = tid & 31;
    int tm = (tid >> 4) * 8, tn = (tid & 15) * 4;
    float acc[8][4];
    #pragma unroll
    for (int i = 0; i < 8; i++)
        #pragma unroll
        for (int j = 0; j < 4; j++) acc[i][j] = 0.f;
    for (int k0 = 0; k0 < K; k0 += 8) {
        float4 av = make_float4(0.f,0.f,0.f,0.f);
        if (arow < M)
            av = *(const float4*)(W + (size_t)arow*K + k0 + acol);
        As[acol+0][arow] = av.x; As[acol+1][arow] = av.y;
        As[acol+2][arow] = av.z; As[acol+3][arow] = av.w;
        Bs[brow][bcol]    = X[(size_t)(k0+brow)*N + bn + bcol];
        Bs[brow][bcol+32] = X[(size_t)(k0+brow)*N + bn + bcol + 32];
        __syncthreads();
        #pragma unroll
        for (int kk = 0; kk < 8; kk++) {
            float a[8], bb[4];
            *(float4*)(a)   = *(const float4*)&As[kk][tm];
            *(float4*)(a+4) = *(const float4*)&As[kk][tm+4];
            *(float4*)(bb)  = *(const float4*)&Bs[kk][tn];
            #pragma unroll
            for (int i = 0; i < 8; i++)
                #pragma unroll
                for (int j = 0; j < 4; j++)
                    acc[i][j] = fmaf(a[i], bb[j], acc[i][j]);
        }
        __syncthreads();
    }
    if (tm < 64) {
        #pragma unroll
        for (int i = 0; i < 8; i++) {
            int row = tm + i;
            #pragma unroll
            for (int j = 0; j < 4; j++) {
                int n = bn + tn + j;
                int q = n & 1023;
                int tok = (n & ~1023) + ((q & 31) << 5) + (q >> 5);
                float y = acc[i][j];
                __nv_bfloat16 h = __float2bfloat16(y);
                dh[(size_t)tok*64 + row] = h;
                dl[(size_t)tok*64 + row] = __float2bfloat16(y - __bfloat162float(h));
            }
        }
    }
}

// ------------------------------ dw7: 1x4 strips + fused transpose ----------
__global__ void dw7_kernel(const float* __restrict__ in, const float* __restrict__ wt,
                           const float* __restrict__ bias,
                           float* __restrict__ out, float* __restrict__ outT) {
    int d = blockIdx.x, b = blockIdx.y;
    __shared__ float sm[38][39];
    __shared__ float wsm[49];
    __shared__ float zt[32][33];
    const float* plane = in + (size_t)d*NTOT + b*NPIX;
    int tid = threadIdx.x;
    if (tid < 49) wsm[tid] = wt[d*49 + tid];
    for (int i = tid; i < 38*38; i += 256) {
        int y = i/38, x = i - y*38;
        int yy = y - 3, xx = x - 3;
        sm[y][x] = (yy>=0 && yy<32 && xx>=0 && xx<32) ? plane[yy*32+xx] : 0.f;
    }
    __syncthreads();
    float bv = bias[d];
    int y  = tid >> 3;
    int x0 = (tid & 7) << 2;
    float a0 = bv, a1 = bv, a2 = bv, a3 = bv;
    #pragma unroll
    for (int ky = 0; ky < 7; ky++) {
        float r[10];
        #pragma unroll
        for (int i = 0; i < 10; i++) r[i] = sm[y+ky][x0+i];
        #pragma unroll
        for (int kx = 0; kx < 7; kx++) {
            float wv = wsm[ky*7+kx];
            a0 = fmaf(r[kx],   wv, a0);
            a1 = fmaf(r[kx+1], wv, a1);
            a2 = fmaf(r[kx+2], wv, a2);
            a3 = fmaf(r[kx+3], wv, a3);
        }
    }
    size_t base = (size_t)d*NTOT + b*NPIX;
    *(float4*)(out + base + (y << 5) + x0) = make_float4(a0, a1, a2, a3);
    zt[y][x0] = a0; zt[y][x0+1] = a1; zt[y][x0+2] = a2; zt[y][x0+3] = a3;
    __syncthreads();
    float4 vt = make_float4(zt[x0][y], zt[x0+1][y], zt[x0+2][y], zt[x0+3][y]);
    *(float4*)(outT + base + (y << 5) + x0) = vt;
}

// ------------------------------ dw3 + y*relu(y): 1x4 strips ----------------
__global__ void dw3act_kernel(const float* __restrict__ in, const float* __restrict__ wt,
                              float* __restrict__ out) {
    int d = blockIdx.x, b = blockIdx.y;
    __shared__ float sm[34][35];
    __shared__ float wsm[9];
    const float* plane = in + (size_t)d*NTOT + b*NPIX;
    int tid = threadIdx.x;
    if (tid < 9) wsm[tid] = wt[d*9 + tid];
    for (int i = tid; i < 34*34; i += 256) {
        int y = i/34, x = i - y*34;
        int yy = y - 1, xx = x - 1;
        sm[y][x] = (yy>=0 && yy<32 && xx>=0 && xx<32) ? plane[yy*32+xx] : 0.f;
    }
    __syncthreads();
    int y  = tid >> 3;
    int x0 = (tid & 7) << 2;
    float a0 = 0.f, a1 = 0.f, a2 = 0.f, a3 = 0.f;
    #pragma unroll
    for (int ky = 0; ky < 3; ky++) {
        float r[6];
        #pragma unroll
        for (int i = 0; i < 6; i++) r[i] = sm[y+ky][x0+i];
        #pragma unroll
        for (int kx = 0; kx < 3; kx++) {
            float wv = wsm[ky*3+kx];
            a0 = fmaf(r[kx],   wv, a0);
            a1 = fmaf(r[kx+1], wv, a1);
            a2 = fmaf(r[kx+2], wv, a2);
            a3 = fmaf(r[kx+3], wv, a3);
        }
    }
    float z0 = (a0 > 0.f) ? a0*a0 : 0.f;
    float z1 = (a1 > 0.f) ? a1*a1 : 0.f;
    float z2 = (a2 > 0.f) ? a2*a2 : 0.f;
    float z3 = (a3 > 0.f) ? a3*a3 : 0.f;
    *(float4*)(out + (size_t)d*NTOT + b*NPIX + (y << 5) + x0) =
        make_float4(z0, z1, z2, z3);
}

// ------------------------------ scan ---------------------------------------
__global__ void scan_kernel(const __nv_bfloat16* __restrict__ gsig,
                            const __half* __restrict__ glud,
                            const float* __restrict__ x2,
                            const float* __restrict__ x2t,
                            const float* __restrict__ mw,
                            __half* __restrict__ s4) {
    int c4 = blockIdx.x, b = blockIdx.y;
    int k = c4 / Dch, d = c4 - k*Dch;
    int tid = threadIdx.x;
    int chunk = tid >> 5, h = tid & 31;
    const size_t PS = (size_t)C4 * NTOT;
    const __nv_bfloat16* Gl = gsig + (size_t)c4*NTOT + (size_t)b*NPIX;
    const __nv_bfloat16* Gm = Gl + PS;
    const __nv_bfloat16* Gr = Gl + 2*PS;
    const __half* Lp = glud + (size_t)c4*NTOT + (size_t)b*NPIX;
    const __half* Up = Lp + PS;
    const __half* Dp = Lp + 2*PS;
    const float* xsrc = ((k & 1) ? x2 : x2t) + (size_t)d*NTOT + b*NPIX;
    float mk = mw[k];
    __half* outp = s4 + (size_t)c4*NTOT + b*NPIX;
    float hs = 0.f;
    const unsigned mask = 0xFFFFFFFFu;
    #pragma unroll
    for (int pos = 0; pos < 8; pos++) {
        int w  = chunk*8 + pos;
        int q  = w*32 + h;
        int wq = (k >= 2) ? (31 - w) : w;
        float xv = xsrc[wq*32 + h];
        float a  = __bfloat162float(Gl[q]);
        float bb = __bfloat162float(Gm[q]);
        float cc = __bfloat162float(Gr[q]);
        float l  = __half2float(Lp[q]);
        float ea = fast_exp(a), eb = fast_exp(bb), ec = fast_exp(cc);
        float qa = 1.f + ea, qb = 1.f + eb, qc = 1.f + ec;
        float pl = ea*qb*qc, pm = eb*qa*qc, pr = ec*qa*qb;
        float den = pl + pm + pr;
        if (h == 0)  den = pm + pr;
        if (h == 31) den = pl + pm;
        float rd = fast_rcp(den);
        float gl = pl*rd, gm = pm*rd, gr = pr*rd;
        float up = __shfl_up_sync(mask, hs, 1);
        float dn = __shfl_down_sync(mask, hs, 1);
        if (h == 0)  up = 0.f;
        if (h == 31) dn = 0.f;
        hs = fmaf(l, xv, fmaf(gl, up, fmaf(gm, hs, gr*dn)));
        float uv = __half2float(Up[q]), dv = __half2float(Dp[q]);
        outp[q] = __float2half(mk * fmaf(hs, uv, xv*dv));
    }
}

// ------------------------------ merge + transpose + bf16 split -------------
__global__ void merge_split_kernel(const __half* __restrict__ s4,
                                   __nv_bfloat16* __restrict__ dh,
                                   __nv_bfloat16* __restrict__ dl) {
    __shared__ float sm[32][33];
    int d0 = blockIdx.x << 5, b = blockIdx.y;
    int tx = threadIdx.x, ty = threadIdx.y;
    for (int pg = blockIdx.z * 8; pg < blockIdx.z * 8 + 8; pg++) {
        int q = (pg << 5) + tx;
        float v = 0.f;
        #pragma unroll
        for (int k = 0; k < 4; k++)
            v += __half2float(s4[(size_t)(k*Dch + d0 + ty)*NTOT + b*NPIX + q]);
        sm[ty][tx] = v;
        __syncthreads();
        float y = sm[tx][ty];
        __nv_bfloat16 hh = __float2bfloat16(y);
        size_t o = (size_t)(b*NPIX + (ty << 5) + pg) * Dch + d0 + tx;
        dh[o] = hh;
        dl[o] = __float2bfloat16(y - __bfloat162float(hh));
        __syncthreads();
    }
}

// ------------------------------ launch -------------------------------------
extern "C" void kernel_launch(void* const* d_in, const int* in_sizes, int n_in,
                              void* d_out, int out_size) {
    const float* hidden   = (const float*)d_in[0];
    const float* norm_w   = (const float*)d_in[1];
    const float* norm_b   = (const float*)d_in[2];
    const float* in_proj  = (const float*)d_in[3];
    const float* conv7_w  = (const float*)d_in[4];
    const float* conv7_b  = (const float*)d_in[5];
    const float* xdown_w  = (const float*)d_in[6];
    const float* wup_w    = (const float*)d_in[7];
    const float* lup_w    = (const float*)d_in[8];
    const float* uup_w    = (const float*)d_in[9];
    const float* dcoef_w  = (const float*)d_in[10];
    const float* m_w      = (const float*)d_in[11];
    const float* outconv_w  = (const float*)d_in[12];
    const float* outdconv_w = (const float*)d_in[13];
    const float* outproj_w  = (const float*)d_in[14];
    float* outp = (float*)d_out;

    float *x1,*x2,*x2t,*oc,*act;
    __half *glud,*s4,*xlnf,*wihf,*wilf;
    __nv_bfloat16 *gsig,*woh,*wol,*wph,*wpl,*gwh,*gwl,
                  *xpnh,*xpnl,*mnh,*mnl,*anh,*anl;
    cudaGetSymbolAddress((void**)&x1, g_x1);   cudaGetSymbolAddress((void**)&x2, g_x2);
    cudaGetSymbolAddress((void**)&x2t,g_x2t);
    cudaGetSymbolAddress((void**)&gsig,g_gsig);cudaGetSymbolAddress((void**)&glud,g_glud);
    cudaGetSymbolAddress((void**)&s4, g_s4);   cudaGetSymbolAddress((void**)&oc, g_oc);
    cudaGetSymbolAddress((void**)&act,g_act);
    cudaGetSymbolAddress((void**)&xlnf,g_xlnf);
    cudaGetSymbolAddress((void**)&wihf,g_wihf);cudaGetSymbolAddress((void**)&wilf,g_wilf);
    cudaGetSymbolAddress((void**)&woh,g_woh);  cudaGetSymbolAddress((void**)&wol,g_wol);
    cudaGetSymbolAddress((void**)&wph,g_wph);  cudaGetSymbolAddress((void**)&wpl,g_wpl);
    cudaGetSymbolAddress((void**)&gwh,g_gwh);  cudaGetSymbolAddress((void**)&gwl,g_gwl);
    cudaGetSymbolAddress((void**)&xpnh,g_xpnh);cudaGetSymbolAddress((void**)&xpnl,g_xpnl);
    cudaGetSymbolAddress((void**)&mnh,g_mnh);  cudaGetSymbolAddress((void**)&mnl,g_mnl);
    cudaGetSymbolAddress((void**)&anh,g_anh);  cudaGetSymbolAddress((void**)&anl,g_anl);

    const int SMEM_TM64_3 = 3 * 24576;   // 72KB, 3-pass bf16
    const int SMEM_TM64_1 = 3 * 12288;   // 36KB, 1-pass bf16
    const int SMEM_F16    = 3 * 16384;   // 48KB, 2-pass fp16
    cudaFuncSetAttribute(mma_gemm<3,0,64,3>, cudaFuncAttributeMaxDynamicSharedMemorySize, SMEM_TM64_3);
    cudaFuncSetAttribute(mma_gemm<3,2,64,3>, cudaFuncAttributeMaxDynamicSharedMemorySize, SMEM_TM64_3);
    cudaFuncSetAttribute(mma_gemm<1,1,64,3>, cudaFuncAttributeMaxDynamicSharedMemorySize, SMEM_TM64_1);
    cudaFuncSetAttribute(mma_gemm_f16,       cudaFuncAttributeMaxDynamicSharedMemorySize, SMEM_F16);
    dim3 b3232(32, 32);

    // 1a) in_proj weights -> fp16 hi/lo
    wsplit_f16_kernel<<<WSEG_BIG/256, 256>>>(in_proj, wihf, wilf);
    // 1b) remaining weights -> bf16 hi/lo
    wsplit_all_kernel<<<(3*WSEG_BIG + 3*WSEG_SMALL)/256, 256>>>(
        outconv_w, outproj_w, wup_w, lup_w, uup_w, dcoef_w,
        woh, wol, wph, wpl, gwh, gwl);

    // 2) LN -> fp16 single plane
    ln_half_kernel<<<NTOT/8, 256>>>(hidden, norm_w, norm_b, xlnf);

    // 3) shortcut copy
    copy_kernel<<<BTD/1024, 256>>>((const float4*)hidden, (float4*)(outp + BTD));

    // 4) in_proj: fp16 2-pass (BISECT TARGET)   <-- profiled launch shifts to #5
    mma_gemm_f16<<<dim3(NTOT/128, Dch/64), 256, SMEM_F16>>>(
        wihf, wilf, xlnf, x1, Dch, NTOT);

    // 5) dw 7x7 (+ fused w-major transpose)
    dw7_kernel<<<dim3(Dch, Bsz), 256>>>(x1, conv7_w, conv7_b, x2, x2t);

    // 6) xdown + fused remap/split -> xpn hi/lo
    xdown_kernel<<<dim3(NTOT/64, 1), 256>>>(xdown_w, x2, xpnh, xpnl);

    // 7) sigmoid gates: 1-pass bf16 out (TM=64)
    mma_gemm<1,1,64,3><<<dim3(NTOT/128, (3*C4)/64), 256, SMEM_TM64_1>>>(
        gwh, nullptr, xpnh, nullptr, nullptr, gsig, nullptr, 64, NTOT);

    // 8) L|U|D: 3-pass, fp16 storage out (TM=64)
    mma_gemm<3,2,64,3><<<dim3(NTOT/128, (3*C4)/64), 256, SMEM_TM64_3>>>(
        gwh + (size_t)3*C4*64, gwl + (size_t)3*C4*64, xpnh, xpnl,
        nullptr, nullptr, glud, 64, NTOT);

    // 9) scan
    scan_kernel<<<dim3(C4, Bsz), 128>>>(gsig, glud, x2, x2t, m_w, s4);

    // 10) merge + transpose + split -> mn hi/lo
    merge_split_kernel<<<dim3(Dch/32, Bsz, 4), b3232>>>(s4, mnh, mnl);

    // 11) outconv (bf16 3-pass, unchanged)
    mma_gemm<3,0,64,3><<<dim3(NTOT/128, Dch/64), 256, SMEM_TM64_3>>>(
        woh, wol, mnh, mnl, oc, nullptr, nullptr, Dch, NTOT);

    // 12) dw 3x3 + y*relu(y)
    dw3act_kernel<<<dim3(Dch, Bsz), 256>>>(oc, outdconv_w, act);

    // 13) act -> (4096x768) hi/lo
    tconv_kernel<<<dim3(NTOT/32, Dch/32), b3232>>>(act, anh, anl);

    // 14) outproj (bf16 3-pass, unchanged) -> d_out
    mma_gemm<3,0,64,3><<<dim3(Dch/128, NTOT/64), 256, SMEM_TM64_3>>>(
        anh, anl, wph, wpl, outp, nullptr, nullptr, Dch, Dch);
}

// round 14
// speedup vs baseline: 1.1248x; 1.0773x over previous
#include <cuda_runtime.h>
#include <cuda_bf16.h>
#include <cuda_fp16.h>
#include <cstdint>

// ---------------------------------------------------------------------------
// GSPN block. B=4, T=1024, D=768, HW=32, DS=48, CHUNK=8.
// Round 14: fp16 2-pass rolled out to outconv + LUD + sig (validated by the
// round-13 bisect). outproj stays bf16 3-pass for error margin.
// ---------------------------------------------------------------------------

#define Bsz   4
#define Dch   768
#define Tlen  1024
#define DS    48
#define NPIX  1024
#define NTOT  4096
#define C4    (4*Dch)         // 3072
#define MG    (6*C4)          // 18432
#define BTD   (Bsz*Tlen*Dch)

// ------------------------- static scratch ----------------------------------
__device__ float g_x1 [(size_t)Dch*NTOT];
__device__ float g_x2 [(size_t)Dch*NTOT];
__device__ float g_x2t[(size_t)Dch*NTOT];
__device__ __align__(16) __half g_gsig[(size_t)3*C4*NTOT];
__device__ __align__(16) __half g_glud[(size_t)3*C4*NTOT];
__device__ __align__(16) __half g_s4 [(size_t)C4*NTOT];
__device__ float g_oc [(size_t)Dch*NTOT];
__device__ float g_act[(size_t)Dch*NTOT];

__device__ __align__(16) __half g_xlnf[(size_t)NTOT*Dch];
__device__ __align__(16) __half g_wihf[Dch*Dch], g_wilf[Dch*Dch];
__device__ __align__(16) __half g_wohf[Dch*Dch], g_wolf[Dch*Dch];
__device__ __align__(16) __half g_gwhf[(size_t)MG*64], g_gwlf[(size_t)MG*64];
__device__ __align__(16) __half g_xpnf[(size_t)NTOT*64];
__device__ __align__(16) __half g_mnf [(size_t)NTOT*Dch];
__device__ __align__(16) __nv_bfloat16 g_wph[Dch*Dch], g_wpl[Dch*Dch];
__device__ __align__(16) __nv_bfloat16 g_anh[(size_t)NTOT*Dch], g_anl[(size_t)NTOT*Dch];

// ------------------------------ helpers ------------------------------------
__device__ __forceinline__ uint32_t smem_u32(const void* p) {
    uint32_t r;
    asm("{ .reg .u64 t; cvta.to.shared.u64 t, %1; cvt.u32.u64 %0, t; }"
        : "=r"(r) : "l"(p));
    return r;
}
__device__ __forceinline__ void cp16(uint32_t saddr, const void* gptr) {
    asm volatile("cp.async.cg.shared.global [%0], [%1], 16;"
        :: "r"(saddr), "l"(gptr));
}
__device__ __forceinline__ void cp_commit() {
    asm volatile("cp.async.commit_group;" ::: "memory");
}
template<int N>
__device__ __forceinline__ void cp_wait() {
    asm volatile("cp.async.wait_group %0;" :: "n"(N) : "memory");
}
__device__ __forceinline__ void ldm4(uint32_t& r0, uint32_t& r1, uint32_t& r2,
                                     uint32_t& r3, uint32_t addr) {
    asm volatile("ldmatrix.sync.aligned.m8n8.x4.shared.b16 {%0,%1,%2,%3}, [%4];"
        : "=r"(r0), "=r"(r1), "=r"(r2), "=r"(r3) : "r"(addr));
}
__device__ __forceinline__ void mma16816(float* c, const uint32_t* a,
                                         const uint32_t* b) {
    asm volatile("mma.sync.aligned.m16n8k16.row.col.f32.bf16.bf16.f32 "
        "{%0,%1,%2,%3}, {%4,%5,%6,%7}, {%8,%9}, {%0,%1,%2,%3};"
        : "+f"(c[0]), "+f"(c[1]), "+f"(c[2]), "+f"(c[3])
        : "r"(a[0]), "r"(a[1]), "r"(a[2]), "r"(a[3]), "r"(b[0]), "r"(b[1]));
}
__device__ __forceinline__ void mma16816h(float* c, const uint32_t* a,
                                          const uint32_t* b) {
    asm volatile("mma.sync.aligned.m16n8k16.row.col.f32.f16.f16.f32 "
        "{%0,%1,%2,%3}, {%4,%5,%6,%7}, {%8,%9}, {%0,%1,%2,%3};"
        : "+f"(c[0]), "+f"(c[1]), "+f"(c[2]), "+f"(c[3])
        : "r"(a[0]), "r"(a[1]), "r"(a[2]), "r"(a[3]), "r"(b[0]), "r"(b[1]));
}

__device__ __forceinline__ float fast_exp(float x) {
    x = fminf(fmaxf(x, -20.f), 20.f);
    float t = x * 1.4426950408889634f;
    float r = t + 12582912.f;
    int   i = __float_as_int(r) - 0x4B400000;
    float f = t - (r - 12582912.f);
    const float c1=0.69314718056f, c2=0.2402265069f, c3=0.0555041087f,
                c4=0.00961812911f, c5=0.00133335581f;
    float p = fmaf(c5, f, c4);
    p = fmaf(p, f, c3); p = fmaf(p, f, c2); p = fmaf(p, f, c1); p = fmaf(p, f, 1.f);
    return __int_as_float(__float_as_int(p) + (i << 23));
}
__device__ __forceinline__ float fast_rcp(float x) {
    float y = __int_as_float(0x7EF311C3 - __float_as_int(x));
    y = y * (2.0f - x * y);
    y = y * (2.0f - x * y);
    y = y * (2.0f - x * y);
    return y;
}

// ------------------------------ bf16 3-pass GEMM (outproj only) ------------
__global__ __launch_bounds__(256, 3)
void mma_gemm_bf16(const __nv_bfloat16* __restrict__ Ahi, const __nv_bfloat16* __restrict__ Alo,
                   const __nv_bfloat16* __restrict__ Bhi, const __nv_bfloat16* __restrict__ Blo,
                   float* __restrict__ Cf, int Kp, int ldc) {
    extern __shared__ __align__(16) char dsm[];
    const int SA = 64 * 64;
    const int SB = 8192;
    const int SSTAGE = 2 * SA + 2 * SB;
    const int tid  = threadIdx.x;
    const int wid  = tid >> 5, lane = tid & 31;
    const int wm   = (wid >> 2) << 5;
    const int wn   = (wid & 3)  << 5;
    const int bm   = blockIdx.y << 6, bn = blockIdx.x << 7;
    const uint32_t sbase = smem_u32(dsm);
    const int NKB = Kp >> 5;

    auto load_stage = [&](int buf, int kb) {
        const int k0 = kb << 5;
        uint32_t sb = sbase + buf * SSTAGE;
        #pragma unroll
        for (int pl = 0; pl < 2; pl++) {
            const __nv_bfloat16* src = (pl == 0) ? Ahi : Alo;
            uint32_t pb = sb + pl * SA;
            int r = tid >> 2, c = tid & 3;
            cp16(pb + (r << 6) + ((uint32_t)(c ^ ((r >> 1) & 3)) << 4),
                 src + (size_t)(bm + r) * Kp + k0 + (c << 3));
        }
        #pragma unroll
        for (int pl = 0; pl < 2; pl++) {
            const __nv_bfloat16* src = (pl == 0) ? Bhi : Blo;
            uint32_t pb = sb + 2 * SA + pl * SB;
            #pragma unroll
            for (int i = tid; i < 512; i += 256) {
                int r = i >> 2, c = i & 3;
                cp16(pb + (r << 6) + ((uint32_t)(c ^ ((r >> 1) & 3)) << 4),
                     src + (size_t)(bn + r) * Kp + k0 + (c << 3));
            }
        }
        cp_commit();
    };

    float acc[2][4][4];
    #pragma unroll
    for (int i = 0; i < 2; i++)
        #pragma unroll
        for (int j = 0; j < 4; j++)
            #pragma unroll
            for (int q = 0; q < 4; q++) acc[i][j][q] = 0.f;

    const int lrow = (lane & 7) + (((lane >> 3) & 1) << 3);
    const int lchunk = (lane >> 4) & 1;

    load_stage(0, 0);
    if (NKB > 1) load_stage(1, 1);

    for (int kb = 0; kb < NKB; kb++) {
        if (kb < NKB - 1) cp_wait<1>(); else cp_wait<0>();
        __syncthreads();
        if (kb + 2 < NKB) {
            int dst = kb + 2;
            load_stage(dst - (dst / 3) * 3, dst);
        }

        uint32_t sb = sbase + (kb - (kb / 3) * 3) * SSTAGE;
        uint32_t aHb = sb, aLb = sb + SA;
        uint32_t bHb = sb + 2 * SA, bLb = bHb + SB;

        #pragma unroll
        for (int ks = 0; ks < 2; ks++) {
            uint32_t bH[4][2], bL[4][2];
            #pragma unroll
            for (int nt2 = 0; nt2 < 2; nt2++) {
                int r = wn + (nt2 << 4) + lrow;
                uint32_t c = (uint32_t)((ks << 1) + lchunk);
                uint32_t off = ((uint32_t)r << 6) + (((c ^ ((r >> 1) & 3)) << 4));
                uint32_t r0, r1, r2, r3;
                ldm4(r0, r1, r2, r3, bHb + off);
                bH[2*nt2][0] = r0; bH[2*nt2][1] = r2;
                bH[2*nt2+1][0] = r1; bH[2*nt2+1][1] = r3;
                ldm4(r0, r1, r2, r3, bLb + off);
                bL[2*nt2][0] = r0; bL[2*nt2][1] = r2;
                bL[2*nt2+1][0] = r1; bL[2*nt2+1][1] = r3;
            }
            #pragma unroll
            for (int mt = 0; mt < 2; mt++) {
                int r = wm + (mt << 4) + lrow;
                uint32_t c = (uint32_t)((ks << 1) + lchunk);
                uint32_t off = ((uint32_t)r << 6) + (((c ^ ((r >> 1) & 3)) << 4));
                uint32_t aH[4], aL[4];
                ldm4(aH[0], aH[1], aH[2], aH[3], aHb + off);
                ldm4(aL[0], aL[1], aL[2], aL[3], aLb + off);
                #pragma unroll
                for (int nt = 0; nt < 4; nt++)
                    mma16816(acc[mt][nt], aH, bH[nt]);
                #pragma unroll
                for (int nt = 0; nt < 4; nt++)
                    mma16816(acc[mt][nt], aH, bL[nt]);
                #pragma unroll
                for (int nt = 0; nt < 4; nt++)
                    mma16816(acc[mt][nt], aL, bH[nt]);
            }
        }
    }

    const int erow = lane >> 2, ecol = (lane & 3) << 1;
    #pragma unroll
    for (int mt = 0; mt < 2; mt++) {
        int r0 = bm + wm + (mt << 4) + erow;
        #pragma unroll
        for (int nt = 0; nt < 4; nt++) {
            int c0 = bn + wn + (nt << 3) + ecol;
            *(float2*)(Cf + (size_t)r0 * ldc + c0) =
                make_float2(acc[mt][nt][0], acc[mt][nt][1]);
            *(float2*)(Cf + (size_t)(r0 + 8) * ldc + c0) =
                make_float2(acc[mt][nt][2], acc[mt][nt][3]);
        }
    }
}

// ------------------------------ fp16 GEMM (A hi/lo or single, B single) ----
// PASSES=2: C=(Ahi+Alo)@B^T. PASSES=1: C=Ahi@B^T. OUT: 0=fp32, 2=fp16.
// TM=64, 8 warps, BK=32, 3 stages. Plane layout [Ahi | (Alo) | B].
template<int PASSES, int OUT>
__global__ __launch_bounds__(256, 3)
void mma_gemm_f16(const __half* __restrict__ Ahi, const __half* __restrict__ Alo,
                  const __half* __restrict__ B,
                  float* __restrict__ Cf, __half* __restrict__ Ch,
                  int Kp, int ldc) {
    extern __shared__ __align__(16) char dsm[];
    const int SA = 64 * 64;
    const int SSTAGE = PASSES * SA + 8192;
    const int tid  = threadIdx.x;
    const int wid  = tid >> 5, lane = tid & 31;
    const int wm   = (wid >> 2) << 5;
    const int wn   = (wid & 3)  << 5;
    const int bm   = blockIdx.y << 6, bn = blockIdx.x << 7;
    const uint32_t sbase = smem_u32(dsm);
    const int NKB = Kp >> 5;

    auto load_stage = [&](int buf, int kb) {
        const int k0 = kb << 5;
        uint32_t sb = sbase + buf * SSTAGE;
        #pragma unroll
        for (int pl = 0; pl < PASSES; pl++) {
            const __half* src = (pl == 0) ? Ahi : Alo;
            uint32_t pb = sb + pl * SA;
            int r = tid >> 2, c = tid & 3;
            cp16(pb + (r << 6) + ((uint32_t)(c ^ ((r >> 1) & 3)) << 4),
                 src + (size_t)(bm + r) * Kp + k0 + (c << 3));
        }
        {
            uint32_t pb = sb + PASSES * SA;
            #pragma unroll
            for (int i = tid; i < 512; i += 256) {
                int r = i >> 2, c = i & 3;
                cp16(pb + (r << 6) + ((uint32_t)(c ^ ((r >> 1) & 3)) << 4),
                     B + (size_t)(bn + r) * Kp + k0 + (c << 3));
            }
        }
        cp_commit();
    };

    float acc[2][4][4];
    #pragma unroll
    for (int i = 0; i < 2; i++)
        #pragma unroll
        for (int j = 0; j < 4; j++)
            #pragma unroll
            for (int q = 0; q < 4; q++) acc[i][j][q] = 0.f;

    const int lrow = (lane & 7) + (((lane >> 3) & 1) << 3);
    const int lchunk = (lane >> 4) & 1;

    load_stage(0, 0);
    if (NKB > 1) load_stage(1, 1);

    for (int kb = 0; kb < NKB; kb++) {
        if (kb < NKB - 1) cp_wait<1>(); else cp_wait<0>();
        __syncthreads();
        if (kb + 2 < NKB) {
            int dst = kb + 2;
            load_stage(dst - (dst / 3) * 3, dst);
        }

        uint32_t sb = sbase + (kb - (kb / 3) * 3) * SSTAGE;
        uint32_t aHb = sb, aLb = sb + SA, bHb = sb + PASSES * SA;

        #pragma unroll
        for (int ks = 0; ks < 2; ks++) {
            uint32_t bH[4][2];
            #pragma unroll
            for (int nt2 = 0; nt2 < 2; nt2++) {
                int r = wn + (nt2 << 4) + lrow;
                uint32_t c = (uint32_t)((ks << 1) + lchunk);
                uint32_t off = ((uint32_t)r << 6) + (((c ^ ((r >> 1) & 3)) << 4));
                uint32_t r0, r1, r2, r3;
                ldm4(r0, r1, r2, r3, bHb + off);
                bH[2*nt2][0] = r0; bH[2*nt2][1] = r2;
                bH[2*nt2+1][0] = r1; bH[2*nt2+1][1] = r3;
            }
            #pragma unroll
            for (int mt = 0; mt < 2; mt++) {
                int r = wm + (mt << 4) + lrow;
                uint32_t c = (uint32_t)((ks << 1) + lchunk);
                uint32_t off = ((uint32_t)r << 6) + (((c ^ ((r >> 1) & 3)) << 4));
                uint32_t aH[4], aL[4];
                ldm4(aH[0], aH[1], aH[2], aH[3], aHb + off);
                if (PASSES == 2)
                    ldm4(aL[0], aL[1], aL[2], aL[3], aLb + off);
                #pragma unroll
                for (int nt = 0; nt < 4; nt++)
                    mma16816h(acc[mt][nt], aH, bH[nt]);
                if (PASSES == 2) {
                    #pragma unroll
                    for (int nt = 0; nt < 4; nt++)
                        mma16816h(acc[mt][nt], aL, bH[nt]);
                }
            }
        }
    }

    const int erow = lane >> 2, ecol = (lane & 3) << 1;
    #pragma unroll
    for (int mt = 0; mt < 2; mt++) {
        int r0 = bm + wm + (mt << 4) + erow;
        #pragma unroll
        for (int nt = 0; nt < 4; nt++) {
            int c0 = bn + wn + (nt << 3) + ecol;
            if (OUT == 2) {
                __half2 v0, v1;
                v0.x = __float2half(acc[mt][nt][0]);
                v0.y = __float2half(acc[mt][nt][1]);
                v1.x = __float2half(acc[mt][nt][2]);
                v1.y = __float2half(acc[mt][nt][3]);
                *(__half2*)(Ch + (size_t)r0 * ldc + c0) = v0;
                *(__half2*)(Ch + (size_t)(r0 + 8) * ldc + c0) = v1;
            } else {
                *(float2*)(Cf + (size_t)r0 * ldc + c0) =
                    make_float2(acc[mt][nt][0], acc[mt][nt][1]);
                *(float2*)(Cf + (size_t)(r0 + 8) * ldc + c0) =
                    make_float2(acc[mt][nt][2], acc[mt][nt][3]);
            }
        }
    }
}

// ------------------------------ shortcut copy -------------------------------
__global__ void copy_kernel(const float4* __restrict__ s, float4* __restrict__ d) {
    int i = blockIdx.x * 256 + threadIdx.x;
    d[i] = s[i];
}

// ------------------------------ LayerNorm -> fp16 ---------------------------
__global__ void ln_half_kernel(const float* __restrict__ xin, const float* __restrict__ w,
                               const float* __restrict__ bsh,
                               __half* __restrict__ oh) {
    int row = blockIdx.x * 8 + (threadIdx.x >> 5);
    int lane = threadIdx.x & 31;
    const float* r = xin + (size_t)row * Dch;
    float v[24];
    float s = 0.f, s2 = 0.f;
    #pragma unroll
    for (int j = 0; j < 24; j++) { float t = r[lane + j*32]; v[j] = t; s += t; s2 += t*t; }
    #pragma unroll
    for (int o = 16; o; o >>= 1) {
        s  += __shfl_xor_sync(0xFFFFFFFFu, s,  o);
        s2 += __shfl_xor_sync(0xFFFFFFFFu, s2, o);
    }
    float mu = s * (1.f/Dch);
    float rs = rsqrtf(s2 * (1.f/Dch) - mu*mu + 1e-5f);
    #pragma unroll
    for (int j = 0; j < 24; j++) {
        int c = lane + j*32;
        float y = (v[j] - mu) * rs * w[c] + bsh[c];
        oh[(size_t)row*Dch + c] = __float2half(y);
    }
}

// ------------------------------ fp16 weight splits --------------------------
#define WSEG_BIG   589824
#define WSEG_SMALL 196608
__global__ void wsplit_f16_all_kernel(
    const float* __restrict__ in_proj, const float* __restrict__ outconv,
    const float* __restrict__ wup, const float* __restrict__ lup,
    const float* __restrict__ uup, const float* __restrict__ dcoef,
    __half* __restrict__ wihf, __half* __restrict__ wilf,
    __half* __restrict__ wohf, __half* __restrict__ wolf,
    __half* __restrict__ gwhf, __half* __restrict__ gwlf) {
    int idx = blockIdx.x * 256 + threadIdx.x;
    const float* src; __half *dh, *dl; int K, Kp, li;
    if (idx < 2 * WSEG_BIG) {
        int seg = idx / WSEG_BIG; li = idx - seg * WSEG_BIG;
        src = (seg == 0) ? in_proj : outconv;
        dh  = (seg == 0) ? wihf : wohf;
        dl  = (seg == 0) ? wilf : wolf;
        K = Dch; Kp = Dch;
    } else {
        int r = idx - 2 * WSEG_BIG;
        if (r < WSEG_BIG) { src = wup; li = r; dh = gwhf; dl = gwlf; }
        else {
            r -= WSEG_BIG;
            int seg = r / WSEG_SMALL; li = r - seg * WSEG_SMALL;
            src = (seg == 0) ? lup : (seg == 1) ? uup : dcoef;
            size_t off = (size_t)(3 + seg) * C4 * 64;
            dh = gwhf + off; dl = gwlf + off;
        }
        K = DS; Kp = 64;
    }
    int m = li / Kp, k = li - m * Kp;
    float v = (k < K) ? src[(size_t)m * K + k] : 0.f;
    __half h = __float2half(v);
    dh[li] = h;
    dl[li] = __float2half(v - __half2float(h));
}

// outproj -> bf16 hi/lo
__global__ void wsplit_bf16_kernel(const float* __restrict__ src,
                                   __nv_bfloat16* __restrict__ dh,
                                   __nv_bfloat16* __restrict__ dl) {
    int idx = blockIdx.x * 256 + threadIdx.x;
    float v = src[idx];
    __nv_bfloat16 h = __float2bfloat16(v);
    dh[idx] = h;
    dl[idx] = __float2bfloat16(v - __bfloat162float(h));
}

// ------------------------------ transpose + bf16 split (act) ---------------
__global__ void tconv_kernel(const float* __restrict__ src,
                             __nv_bfloat16* __restrict__ dh, __nv_bfloat16* __restrict__ dl) {
    __shared__ float sm[32][33];
    int n0 = blockIdx.x << 5, k0 = blockIdx.y << 5;
    int tx = threadIdx.x, ty = threadIdx.y;
    float v = src[(size_t)(k0 + ty) * NTOT + n0 + tx];
    sm[ty][tx] = v;
    __syncthreads();
    float y = sm[tx][ty];
    __nv_bfloat16 h = __float2bfloat16(y);
    size_t o = (size_t)(n0 + ty) * Dch + k0 + tx;
    dh[o] = h;
    dl[o] = __float2bfloat16(y - __bfloat162float(h));
}

// ------------------------------ xdown + fused remap -> fp16 single ---------
__global__ __launch_bounds__(256)
void xdown_kernel(const float* __restrict__ W, const float* __restrict__ X,
                  __half* __restrict__ dh) {
    __shared__ float As[8][128];
    __shared__ float Bs[8][64];
    const int M = DS, N = NTOT, K = Dch;
    int bn = blockIdx.x * 64;
    int tid = threadIdx.x;
    int arow = tid >> 1, acol = (tid & 1) * 4;
    int brow = tid >> 5, bcol = tid & 31;
    int tm = (tid >> 4) * 8, tn = (tid & 15) * 4;
    float acc[8][4];
    #pragma unroll
    for (int i = 0; i < 8; i++)
        #pragma unroll
        for (int j = 0; j < 4; j++) acc[i][j] = 0.f;
    for (int k0 = 0; k0 < K; k0 += 8) {
        float4 av = make_float4(0.f,0.f,0.f,0.f);
        if (arow < M)
            av = *(const float4*)(W + (size_t)arow*K + k0 + acol);
        As[acol+0][arow] = av.x; As[acol+1][arow] = av.y;
        As[acol+2][arow] = av.z; As[acol+3][arow] = av.w;
        Bs[brow][bcol]    = X[(size_t)(k0+brow)*N + bn + bcol];
        Bs[brow][bcol+32] = X[(size_t)(k0+brow)*N + bn + bcol + 32];
        __syncthreads();
        #pragma unroll
        for (int kk = 0; kk < 8; kk++) {
            float a[8], bb[4];
            *(float4*)(a)   = *(const float4*)&As[kk][tm];
            *(float4*)(a+4) = *(const float4*)&As[kk][tm+4];
            *(float4*)(bb)  = *(const float4*)&Bs[kk][tn];
            #pragma unroll
            for (int i = 0; i < 8; i++)
                #pragma unroll
                for (int j = 0; j < 4; j++)
                    acc[i][j] = fmaf(a[i], bb[j], acc[i][j]);
        }
        __syncthreads();
    }
    if (tm < 64) {
        #pragma unroll
        for (int i = 0; i < 8; i++) {
            int row = tm + i;
            #pragma unroll
            for (int j = 0; j < 4; j++) {
                int n = bn + tn + j;
                int q = n & 1023;
                int tok = (n & ~1023) + ((q & 31) << 5) + (q >> 5);
                dh[(size_t)tok*64 + row] = __float2half(acc[i][j]);
            }
        }
    }
}

// ------------------------------ dw7: 1x4 strips + fused transpose ----------
__global__ void dw7_kernel(const float* __restrict__ in, const float* __restrict__ wt,
                           const float* __restrict__ bias,
                           float* __restrict__ out, float* __restrict__ outT) {
    int d = blockIdx.x, b = blockIdx.y;
    __shared__ float sm[38][39];
    __shared__ float wsm[49];
    __shared__ float zt[32][33];
    const float* plane = in + (size_t)d*NTOT + b*NPIX;
    int tid = threadIdx.x;
    if (tid < 49) wsm[tid] = wt[d*49 + tid];
    for (int i = tid; i < 38*38; i += 256) {
        int y = i/38, x = i - y*38;
        int yy = y - 3, xx = x - 3;
        sm[y][x] = (yy>=0 && yy<32 && xx>=0 && xx<32) ? plane[yy*32+xx] : 0.f;
    }
    __syncthreads();
    float bv = bias[d];
    int y  = tid >> 3;
    int x0 = (tid & 7) << 2;
    float a0 = bv, a1 = bv, a2 = bv, a3 = bv;
    #pragma unroll
    for (int ky = 0; ky < 7; ky++) {
        float r[10];
        #pragma unroll
        for (int i = 0; i < 10; i++) r[i] = sm[y+ky][x0+i];
        #pragma unroll
        for (int kx = 0; kx < 7; kx++) {
            float wv = wsm[ky*7+kx];
            a0 = fmaf(r[kx],   wv, a0);
            a1 = fmaf(r[kx+1], wv, a1);
            a2 = fmaf(r[kx+2], wv, a2);
            a3 = fmaf(r[kx+3], wv, a3);
        }
    }
    size_t base = (size_t)d*NTOT + b*NPIX;
    *(float4*)(out + base + (y << 5) + x0) = make_float4(a0, a1, a2, a3);
    zt[y][x0] = a0; zt[y][x0+1] = a1; zt[y][x0+2] = a2; zt[y][x0+3] = a3;
    __syncthreads();
    float4 vt = make_float4(zt[x0][y], zt[x0+1][y], zt[x0+2][y], zt[x0+3][y]);
    *(float4*)(outT + base + (y << 5) + x0) = vt;
}

// ------------------------------ dw3 + y*relu(y): 1x4 strips ----------------
__global__ void dw3act_kernel(const float* __restrict__ in, const float* __restrict__ wt,
                              float* __restrict__ out) {
    int d = blockIdx.x, b = blockIdx.y;
    __shared__ float sm[34][35];
    __shared__ float wsm[9];
    const float* plane = in + (size_t)d*NTOT + b*NPIX;
    int tid = threadIdx.x;
    if (tid < 9) wsm[tid] = wt[d*9 + tid];
    for (int i = tid; i < 34*34; i += 256) {
        int y = i/34, x = i - y*34;
        int yy = y - 1, xx = x - 1;
        sm[y][x] = (yy>=0 && yy<32 && xx>=0 && xx<32) ? plane[yy*32+xx] : 0.f;
    }
    __syncthreads();
    int y  = tid >> 3;
    int x0 = (tid & 7) << 2;
    float a0 = 0.f, a1 = 0.f, a2 = 0.f, a3 = 0.f;
    #pragma unroll
    for (int ky = 0; ky < 3; ky++) {
        float r[6];
        #pragma unroll
        for (int i = 0; i < 6; i++) r[i] = sm[y+ky][x0+i];
        #pragma unroll
        for (int kx = 0; kx < 3; kx++) {
            float wv = wsm[ky*3+kx];
            a0 = fmaf(r[kx],   wv, a0);
            a1 = fmaf(r[kx+1], wv, a1);
            a2 = fmaf(r[kx+2], wv, a2);
            a3 = fmaf(r[kx+3], wv, a3);
        }
    }
    float z0 = (a0 > 0.f) ? a0*a0 : 0.f;
    float z1 = (a1 > 0.f) ? a1*a1 : 0.f;
    float z2 = (a2 > 0.f) ? a2*a2 : 0.f;
    float z3 = (a3 > 0.f) ? a3*a3 : 0.f;
    *(float4*)(out + (size_t)d*NTOT + b*NPIX + (y << 5) + x0) =
        make_float4(z0, z1, z2, z3);
}

// ------------------------------ scan ---------------------------------------
__global__ void scan_kernel(const __half* __restrict__ gsig,
                            const __half* __restrict__ glud,
                            const float* __restrict__ x2,
                            const float* __restrict__ x2t,
                            const float* __restrict__ mw,
                            __half* __restrict__ s4) {
    int c4 = blockIdx.x, b = blockIdx.y;
    int k = c4 / Dch, d = c4 - k*Dch;
    int tid = threadIdx.x;
    int chunk = tid >> 5, h = tid & 31;
    const size_t PS = (size_t)C4 * NTOT;
    const __half* Gl = gsig + (size_t)c4*NTOT + (size_t)b*NPIX;
    const __half* Gm = Gl + PS;
    const __half* Gr = Gl + 2*PS;
    const __half* Lp = glud + (size_t)c4*NTOT + (size_t)b*NPIX;
    const __half* Up = Lp + PS;
    const __half* Dp = Lp + 2*PS;
    const float* xsrc = ((k & 1) ? x2 : x2t) + (size_t)d*NTOT + b*NPIX;
    float mk = mw[k];
    __half* outp = s4 + (size_t)c4*NTOT + b*NPIX;
    float hs = 0.f;
    const unsigned mask = 0xFFFFFFFFu;
    #pragma unroll
    for (int pos = 0; pos < 8; pos++) {
        int w  = chunk*8 + pos;
        int q  = w*32 + h;
        int wq = (k >= 2) ? (31 - w) : w;
        float xv = xsrc[wq*32 + h];
        float a  = __half2float(Gl[q]);
        float bb = __half2float(Gm[q]);
        float cc = __half2float(Gr[q]);
        float l  = __half2float(Lp[q]);
        float ea = fast_exp(a), eb = fast_exp(bb), ec = fast_exp(cc);
        float qa = 1.f + ea, qb = 1.f + eb, qc = 1.f + ec;
        float pl = ea*qb*qc, pm = eb*qa*qc, pr = ec*qa*qb;
        float den = pl + pm + pr;
        if (h == 0)  den = pm + pr;
        if (h == 31) den = pl + pm;
        float rd = fast_rcp(den);
        float gl = pl*rd, gm = pm*rd, gr = pr*rd;
        float up = __shfl_up_sync(mask, hs, 1);
        float dn = __shfl_down_sync(mask, hs, 1);
        if (h == 0)  up = 0.f;
        if (h == 31) dn = 0.f;
        hs = fmaf(l, xv, fmaf(gl, up, fmaf(gm, hs, gr*dn)));
        float uv = __half2float(Up[q]), dv = __half2float(Dp[q]);
        outp[q] = __float2half(mk * fmaf(hs, uv, xv*dv));
    }
}

// ------------------------------ merge + transpose -> fp16 single -----------
__global__ void merge_half_kernel(const __half* __restrict__ s4,
                                  __half* __restrict__ dh) {
    __shared__ float sm[32][33];
    int d0 = blockIdx.x << 5, b = blockIdx.y;
    int tx = threadIdx.x, ty = threadIdx.y;
    for (int pg = blockIdx.z * 8; pg < blockIdx.z * 8 + 8; pg++) {
        int q = (pg << 5) + tx;
        float v = 0.f;
        #pragma unroll
        for (int k = 0; k < 4; k++)
            v += __half2float(s4[(size_t)(k*Dch + d0 + ty)*NTOT + b*NPIX + q]);
        sm[ty][tx] = v;
        __syncthreads();
        dh[(size_t)(b*NPIX + (ty << 5) + pg) * Dch + d0 + tx] =
            __float2half(sm[tx][ty]);
        __syncthreads();
    }
}

// ------------------------------ launch -------------------------------------
extern "C" void kernel_launch(void* const* d_in, const int* in_sizes, int n_in,
                              void* d_out, int out_size) {
    const float* hidden   = (const float*)d_in[0];
    const float* norm_w   = (const float*)d_in[1];
    const float* norm_b   = (const float*)d_in[2];
    const float* in_proj  = (const float*)d_in[3];
    const float* conv7_w  = (const float*)d_in[4];
    const float* conv7_b  = (const float*)d_in[5];
    const float* xdown_w  = (const float*)d_in[6];
    const float* wup_w    = (const float*)d_in[7];
    const float* lup_w    = (const float*)d_in[8];
    const float* uup_w    = (const float*)d_in[9];
    const float* dcoef_w  = (const float*)d_in[10];
    const float* m_w      = (const float*)d_in[11];
    const float* outconv_w  = (const float*)d_in[12];
    const float* outdconv_w = (const float*)d_in[13];
    const float* outproj_w  = (const float*)d_in[14];
    float* outp = (float*)d_out;

    float *x1,*x2,*x2t,*oc,*act;
    __half *gsig,*glud,*s4,*xlnf,*wihf,*wilf,*wohf,*wolf,*gwhf,*gwlf,*xpnf,*mnf;
    __nv_bfloat16 *wph,*wpl,*anh,*anl;
    cudaGetSymbolAddress((void**)&x1, g_x1);   cudaGetSymbolAddress((void**)&x2, g_x2);
    cudaGetSymbolAddress((void**)&x2t,g_x2t);
    cudaGetSymbolAddress((void**)&gsig,g_gsig);cudaGetSymbolAddress((void**)&glud,g_glud);
    cudaGetSymbolAddress((void**)&s4, g_s4);   cudaGetSymbolAddress((void**)&oc, g_oc);
    cudaGetSymbolAddress((void**)&act,g_act);
    cudaGetSymbolAddress((void**)&xlnf,g_xlnf);
    cudaGetSymbolAddress((void**)&wihf,g_wihf);cudaGetSymbolAddress((void**)&wilf,g_wilf);
    cudaGetSymbolAddress((void**)&wohf,g_wohf);cudaGetSymbolAddress((void**)&wolf,g_wolf);
    cudaGetSymbolAddress((void**)&gwhf,g_gwhf);cudaGetSymbolAddress((void**)&gwlf,g_gwlf);
    cudaGetSymbolAddress((void**)&xpnf,g_xpnf);cudaGetSymbolAddress((void**)&mnf, g_mnf);
    cudaGetSymbolAddress((void**)&wph,g_wph);  cudaGetSymbolAddress((void**)&wpl,g_wpl);
    cudaGetSymbolAddress((void**)&anh,g_anh);  cudaGetSymbolAddress((void**)&anl,g_anl);

    const int SMEM_BF3 = 3 * 24576;   // 72KB bf16 3-pass TM=64
    const int SMEM_F2  = 3 * 16384;   // 48KB fp16 2-pass
    const int SMEM_F1  = 3 * 12288;   // 36KB fp16 1-pass
    cudaFuncSetAttribute(mma_gemm_bf16,     cudaFuncAttributeMaxDynamicSharedMemorySize, SMEM_BF3);
    cudaFuncSetAttribute(mma_gemm_f16<2,0>, cudaFuncAttributeMaxDynamicSharedMemorySize, SMEM_F2);
    cudaFuncSetAttribute(mma_gemm_f16<2,2>, cudaFuncAttributeMaxDynamicSharedMemorySize, SMEM_F2);
    cudaFuncSetAttribute(mma_gemm_f16<1,2>, cudaFuncAttributeMaxDynamicSharedMemorySize, SMEM_F1);
    dim3 b3232(32, 32);

    // 1a) fp16 weight splits (in_proj, outconv, gate weights)
    wsplit_f16_all_kernel<<<(3*WSEG_BIG + 3*WSEG_SMALL)/256, 256>>>(
        in_proj, outconv_w, wup_w, lup_w, uup_w, dcoef_w,
        wihf, wilf, wohf, wolf, gwhf, gwlf);
    // 1b) outproj -> bf16 hi/lo
    wsplit_bf16_kernel<<<WSEG_BIG/256, 256>>>(outproj_w, wph, wpl);

    // 2) LN -> fp16
    ln_half_kernel<<<NTOT/8, 256>>>(hidden, norm_w, norm_b, xlnf);

    // 3) shortcut copy
    copy_kernel<<<BTD/1024, 256>>>((const float4*)hidden, (float4*)(outp + BTD));

    // 4) in_proj: fp16 2-pass
    mma_gemm_f16<2,0><<<dim3(NTOT/128, Dch/64), 256, SMEM_F2>>>(
        wihf, wilf, xlnf, x1, nullptr, Dch, NTOT);

    // 5) dw 7x7 (+ fused w-major transpose)
    dw7_kernel<<<dim3(Dch, Bsz), 256>>>(x1, conv7_w, conv7_b, x2, x2t);

    // 6) xdown + fused remap -> xpn fp16 single
    xdown_kernel<<<dim3(NTOT/64, 1), 256>>>(xdown_w, x2, xpnf);

    // 7) sigmoid gates: fp16 1-pass, fp16 out
    mma_gemm_f16<1,2><<<dim3(NTOT/128, (3*C4)/64), 256, SMEM_F1>>>(
        gwhf, nullptr, xpnf, nullptr, gsig, 64, NTOT);

    // 8) L|U|D: fp16 2-pass, fp16 out
    mma_gemm_f16<2,2><<<dim3(NTOT/128, (3*C4)/64), 256, SMEM_F2>>>(
        gwhf + (size_t)3*C4*64, gwlf + (size_t)3*C4*64, xpnf,
        nullptr, glud, 64, NTOT);

    // 9) scan
    scan_kernel<<<dim3(C4, Bsz), 128>>>(gsig, glud, x2, x2t, m_w, s4);

    // 10) merge + transpose -> mn fp16 single
    merge_half_kernel<<<dim3(Dch/32, Bsz, 4), b3232>>>(s4, mnf);

    // 11) outconv: fp16 2-pass
    mma_gemm_f16<2,0><<<dim3(NTOT/128, Dch/64), 256, SMEM_F2>>>(
        wohf, wolf, mnf, oc, nullptr, Dch, NTOT);

    // 12) dw 3x3 + y*relu(y)
    dw3act_kernel<<<dim3(Dch, Bsz), 256>>>(oc, outdconv_w, act);

    // 13) act -> bf16 hi/lo (outproj stays bf16 3-pass)
    tconv_kernel<<<dim3(NTOT/32, Dch/32), b3232>>>(act, anh, anl);

    // 14) outproj: bf16 3-pass -> d_out
    mma_gemm_bf16<<<dim3(Dch/128, NTOT/64), 256, SMEM_BF3>>>(
        anh, anl, wph, wpl, outp, Dch, Dch);
}